// round 11
// baseline (speedup 1.0000x reference)
#include <cuda_runtime.h>
#include <cuda_bf16.h>
#include <cstdint>

#define BATCH   2
#define SEQ     2048
#define HIDDEN  1024
#define HEADS   16
#define HDIM    64
#define NTOK    (BATCH * SEQ)          // 4096
#define QK_SCALE2 0.18033688f           // 0.125 * log2(e)

typedef __nv_bfloat16 bf16;

// ---------------------------------------------------------------------------
// Device scratch (no cudaMalloc allowed)
// ---------------------------------------------------------------------------
__device__ bf16 s_xhi[NTOK * HIDDEN];               // X split-bf16
__device__ bf16 s_xlo[NTOK * HIDDEN];
__device__ bf16 s_whi[4 * HIDDEN * HIDDEN];         // W^T split-bf16 (q,k,v,o)
__device__ bf16 s_wlo[4 * HIDDEN * HIDDEN];
__device__ bf16 g_qhi[BATCH * HEADS * SEQ * HDIM];  // [B,H,S,D] (Q pre-scaled)
__device__ bf16 g_qlo[BATCH * HEADS * SEQ * HDIM];
__device__ bf16 g_khi[BATCH * HEADS * SEQ * HDIM];
__device__ bf16 g_klo[BATCH * HEADS * SEQ * HDIM];
__device__ bf16 g_vhi[BATCH * HEADS * SEQ * HDIM];
__device__ bf16 g_vlo[BATCH * HEADS * SEQ * HDIM];
__device__ bf16 g_ohi[NTOK * HIDDEN];               // attention out [B,S,H*D]
__device__ bf16 g_olo[NTOK * HIDDEN];

// ---------------------------------------------------------------------------
// PTX helpers
// ---------------------------------------------------------------------------
__device__ __forceinline__ uint32_t smem_u32(const void* p) {
    uint32_t a;
    asm("{ .reg .u64 t; cvta.to.shared.u64 t, %1; cvt.u32.u64 %0, t; }" : "=r"(a) : "l"(p));
    return a;
}
__device__ __forceinline__ void cp16(uint32_t s, const void* g) {
    asm volatile("cp.async.cg.shared.global [%0], [%1], 16;" :: "r"(s), "l"(g) : "memory");
}
#define CP_COMMIT() asm volatile("cp.async.commit_group;" ::: "memory")
#define CP_WAIT0()  asm volatile("cp.async.wait_group 0;" ::: "memory")
#define CP_WAIT1()  asm volatile("cp.async.wait_group 1;" ::: "memory")

__device__ __forceinline__ void ldsm4(uint32_t& r0, uint32_t& r1, uint32_t& r2, uint32_t& r3, uint32_t a) {
    asm volatile("ldmatrix.sync.aligned.m8n8.x4.shared.b16 {%0,%1,%2,%3}, [%4];"
                 : "=r"(r0), "=r"(r1), "=r"(r2), "=r"(r3) : "r"(a));
}
__device__ __forceinline__ void ldsm4t(uint32_t& r0, uint32_t& r1, uint32_t& r2, uint32_t& r3, uint32_t a) {
    asm volatile("ldmatrix.sync.aligned.m8n8.x4.trans.shared.b16 {%0,%1,%2,%3}, [%4];"
                 : "=r"(r0), "=r"(r1), "=r"(r2), "=r"(r3) : "r"(a));
}
__device__ __forceinline__ void mma_bf16(float d[4], const uint32_t a[4], const uint32_t b[2]) {
    asm volatile(
        "mma.sync.aligned.m16n8k16.row.col.f32.bf16.bf16.f32 "
        "{%0,%1,%2,%3}, {%4,%5,%6,%7}, {%8,%9}, {%0,%1,%2,%3};"
        : "+f"(d[0]), "+f"(d[1]), "+f"(d[2]), "+f"(d[3])
        : "r"(a[0]), "r"(a[1]), "r"(a[2]), "r"(a[3]), "r"(b[0]), "r"(b[1]));
}
// split x,y into packed bf16 hi pair + lo pair (packed cvt)
__device__ __forceinline__ void hilo2(float x, float y, uint32_t& hi, uint32_t& lo) {
    __nv_bfloat162 h2 = __floats2bfloat162_rn(x, y);   // x->low, y->high
    float rx = x - __bfloat162float(h2.x);
    float ry = y - __bfloat162float(h2.y);
    __nv_bfloat162 l2 = __floats2bfloat162_rn(rx, ry);
    hi = *reinterpret_cast<uint32_t*>(&h2);
    lo = *reinterpret_cast<uint32_t*>(&l2);
}

// ---------------------------------------------------------------------------
// Pre-convert kernels
// ---------------------------------------------------------------------------
__global__ __launch_bounds__(256) void convert_x(const float* __restrict__ X) {
    size_t i4 = ((size_t)blockIdx.x * 256 + threadIdx.x) * 4;
    float4 v = *(const float4*)&X[i4];
    uint32_t h0, l0, h1, l1;
    hilo2(v.x, v.y, h0, l0);
    hilo2(v.z, v.w, h1, l1);
    *(uint32_t*)&s_xhi[i4]     = h0;  *(uint32_t*)&s_xhi[i4 + 2] = h1;
    *(uint32_t*)&s_xlo[i4]     = l0;  *(uint32_t*)&s_xlo[i4 + 2] = l1;
}

// W [k][n] -> Wt [n][k] split-bf16, 32x32 tiles
__global__ __launch_bounds__(256) void transpose_w(
    const float* __restrict__ w0, const float* __restrict__ w1,
    const float* __restrict__ w2, const float* __restrict__ w3)
{
    __shared__ float t[32][33];
    const int z = blockIdx.z;
    const float* W = (z == 0) ? w0 : (z == 1) ? w1 : (z == 2) ? w2 : w3;
    const size_t zoff = (size_t)z * HIDDEN * HIDDEN;
    const int n0 = blockIdx.x * 32, k0 = blockIdx.y * 32;
    const int tx = threadIdx.x, ty = threadIdx.y;   // 32 x 8
#pragma unroll
    for (int i = 0; i < 4; i++)
        t[ty + i * 8][tx] = W[(size_t)(k0 + ty + i * 8) * HIDDEN + n0 + tx];
    __syncthreads();
#pragma unroll
    for (int i = 0; i < 4; i++) {
        int nr = ty + i * 8;
        float v = t[tx][nr];
        bf16 h = __float2bfloat16_rn(v);
        bf16 l = __float2bfloat16_rn(v - __bfloat162float(h));
        s_whi[zoff + (size_t)(n0 + nr) * HIDDEN + k0 + tx] = h;
        s_wlo[zoff + (size_t)(n0 + nr) * HIDDEN + k0 + tx] = l;
    }
}

// ---------------------------------------------------------------------------
// Split-bf16 GEMM: C[4096x1024] = A @ Wt^T ; A,Wt row-major bf16 hi/lo.
// Block 128x128xBK32, 2-stage cp.async, 8 warps (warp tile 64x32), 2 CTAs/SM.
// Per-CTA k-rotation decorrelates cross-CTA load bursts; B-frags held,
// A-frags streamed (low register liveness under the 128-reg cap).
// ---------------------------------------------------------------------------
#define GBK     32
#define GKITERS (HIDDEN / GBK)          // 32
#define GSTR    80                      // bytes per smem row (40 bf16, pad)
#define GT_B    (128 * GSTR)            // 10240 per matrix tile
#define OA_HI   0
#define OA_LO   GT_B
#define OB_HI   (2 * GT_B)
#define OB_LO   (3 * GT_B)
#define GSTAGE_B (4 * GT_B)             // 40960
#define GSMEM   (2 * GSTAGE_B)          // 81920 (x2 CTAs = 160K)

__device__ __forceinline__ void gemm_load_stage(
    uint32_t sb, const bf16* __restrict__ Ahi, const bf16* __restrict__ Alo,
    const bf16* __restrict__ Bhi, const bf16* __restrict__ Blo,
    int row0, int col0, int kc, int tid)
{
    const int k0 = kc * GBK;
#pragma unroll
    for (int i = 0; i < 2; i++) {
        int idx = tid + i * 256;        // 512 chunks per matrix
        int r = idx >> 2, c = idx & 3;  // r 0..127, c 0..3 (16B chunks)
        uint32_t so = (uint32_t)(r * GSTR + c * 16);
        size_t ga = (size_t)(row0 + r) * HIDDEN + k0 + c * 8;
        size_t gb = (size_t)(col0 + r) * HIDDEN + k0 + c * 8;
        cp16(sb + OA_HI + so, &Ahi[ga]);
        cp16(sb + OA_LO + so, &Alo[ga]);
        cp16(sb + OB_HI + so, &Bhi[gb]);
        cp16(sb + OB_LO + so, &Blo[gb]);
    }
}

__device__ __forceinline__ void gemm_body(
    const bf16* __restrict__ Ahi, const bf16* __restrict__ Alo,
    const bf16* __restrict__ Bhi, const bf16* __restrict__ Blo,
    bf16* __restrict__ OutHi, bf16* __restrict__ OutLo,   // mode qkv (permuted)
    float* __restrict__ OutF,                             // mode fp32 row-major
    float oscale)
{
    extern __shared__ __align__(16) char gsm[];
    const uint32_t sb0 = smem_u32(gsm);

    const int tid = threadIdx.x;        // 256 threads
    const int lane = tid & 31;
    const int wid = tid >> 5;           // 0..7
    const int g = lane >> 2, tig = lane & 3;
    const int warp_m = wid >> 2;        // 0..1 (64 rows)
    const int warp_n = wid & 3;         // 0..3 (32 cols)
    const int row0 = blockIdx.y * 128;
    const int col0 = blockIdx.x * 128;
    // per-CTA k-rotation (commutative accumulation) to decorrelate L2 bursts
    const int krot = (int)((blockIdx.y * 5 + blockIdx.x * 9 + blockIdx.z * 11) & 31);

    float acc[4][4][4];
#pragma unroll
    for (int mi = 0; mi < 4; mi++)
#pragma unroll
        for (int ni = 0; ni < 4; ni++)
#pragma unroll
            for (int e = 0; e < 4; e++) acc[mi][ni][e] = 0.f;

    gemm_load_stage(sb0, Ahi, Alo, Bhi, Blo, row0, col0, krot, tid);
    CP_COMMIT();

    const uint32_t a_row = (uint32_t)(((lane >> 3) & 1) * 8 + (lane & 7));
    const uint32_t a_cb  = (uint32_t)((lane >> 4) * 16);
    const uint32_t b_row = (uint32_t)((lane >> 4) * 8 + (lane & 7));
    const uint32_t b_cb  = (uint32_t)(((lane >> 3) & 1) * 16);

    for (int it = 0; it < GKITERS; it++) {
        CP_WAIT0();
        __syncthreads();
        if (it + 1 < GKITERS)
            gemm_load_stage(sb0 + ((it + 1) & 1) * GSTAGE_B, Ahi, Alo, Bhi, Blo,
                            row0, col0, (it + 1 + krot) & 31, tid);
        CP_COMMIT();

        const uint32_t sb = sb0 + (it & 1) * GSTAGE_B;
#pragma unroll
        for (int ks = 0; ks < 2; ks++) {           // two k16 slices
            const uint32_t cbA = (uint32_t)(ks * 32) + a_cb;
            const uint32_t cbB = (uint32_t)(ks * 32) + b_cb;

            // B fragments held for the slice (16 regs)
            uint32_t bh0[2][2], bh1[2][2], bl0[2][2], bl1[2][2];
#pragma unroll
            for (int np = 0; np < 2; np++) {
                uint32_t n = (uint32_t)(warp_n * 32 + np * 16) + b_row;
                uint32_t bd = sb + n * GSTR + cbB;
                uint32_t h0, h1, h2, h3, l0, l1, l2, l3;
                ldsm4(h0, h1, h2, h3, bd + OB_HI);
                ldsm4(l0, l1, l2, l3, bd + OB_LO);
                bh0[np][0] = h0; bh0[np][1] = h1;
                bh1[np][0] = h2; bh1[np][1] = h3;
                bl0[np][0] = l0; bl0[np][1] = l1;
                bl1[np][0] = l2; bl1[np][1] = l3;
            }

            // A fragments streamed per-mi with one-ahead prefetch (16 regs)
            uint32_t ahA[4], alA[4], ahB[4], alB[4];
            {
                uint32_t r = (uint32_t)(warp_m * 64) + a_row;
                uint32_t ad = sb + r * GSTR + cbA;
                ldsm4(ahA[0], ahA[1], ahA[2], ahA[3], ad + OA_HI);
                ldsm4(alA[0], alA[1], alA[2], alA[3], ad + OA_LO);
            }
#pragma unroll
            for (int mi = 0; mi < 4; mi++) {
                uint32_t* ah = (mi & 1) ? ahB : ahA;
                uint32_t* al = (mi & 1) ? alB : alA;
                uint32_t* ahN = (mi & 1) ? ahA : ahB;
                uint32_t* alN = (mi & 1) ? alA : alB;
                if (mi < 3) {
                    uint32_t r = (uint32_t)(warp_m * 64 + (mi + 1) * 16) + a_row;
                    uint32_t ad = sb + r * GSTR + cbA;
                    ldsm4(ahN[0], ahN[1], ahN[2], ahN[3], ad + OA_HI);
                    ldsm4(alN[0], alN[1], alN[2], alN[3], ad + OA_LO);
                }
#pragma unroll
                for (int np = 0; np < 2; np++) {
                    mma_bf16(acc[mi][np * 2],     ah, bh0[np]);
                    mma_bf16(acc[mi][np * 2],     ah, bl0[np]);
                    mma_bf16(acc[mi][np * 2],     al, bh0[np]);
                    mma_bf16(acc[mi][np * 2 + 1], ah, bh1[np]);
                    mma_bf16(acc[mi][np * 2 + 1], ah, bl1[np]);
                    mma_bf16(acc[mi][np * 2 + 1], al, bh1[np]);
                }
            }
        }
    }

    // epilogue
#pragma unroll
    for (int mi = 0; mi < 4; mi++) {
        int r = row0 + warp_m * 64 + mi * 16 + g;       // rows r, r+8
#pragma unroll
        for (int ni = 0; ni < 4; ni++) {
            int col = col0 + warp_n * 32 + ni * 8 + tig * 2;
            if (OutF) {
                *(float2*)&OutF[(size_t)r * HIDDEN + col] =
                    make_float2(acc[mi][ni][0], acc[mi][ni][1]);
                *(float2*)&OutF[(size_t)(r + 8) * HIDDEN + col] =
                    make_float2(acc[mi][ni][2], acc[mi][ni][3]);
            } else {
                int h = col >> 6, d = col & 63;
                int b0 = r >> 11, s0 = r & 2047;
                int b1 = (r + 8) >> 11, s1 = (r + 8) & 2047;
                size_t i0 = (((size_t)(b0 * HEADS + h)) * SEQ + s0) * HDIM + d;
                size_t i1 = (((size_t)(b1 * HEADS + h)) * SEQ + s1) * HDIM + d;
                uint32_t hi, lo;
                hilo2(acc[mi][ni][0] * oscale, acc[mi][ni][1] * oscale, hi, lo);
                *(uint32_t*)&OutHi[i0] = hi;  *(uint32_t*)&OutLo[i0] = lo;
                hilo2(acc[mi][ni][2] * oscale, acc[mi][ni][3] * oscale, hi, lo);
                *(uint32_t*)&OutHi[i1] = hi;  *(uint32_t*)&OutLo[i1] = lo;
            }
        }
    }
}

__global__ __launch_bounds__(256, 2) void gemm_qkv() {
    const int z = blockIdx.z;
    const size_t zoff = (size_t)z * HIDDEN * HIDDEN;
    bf16* oh = (z == 0) ? g_qhi : (z == 1) ? g_khi : g_vhi;
    bf16* ol = (z == 0) ? g_qlo : (z == 1) ? g_klo : g_vlo;
    float sc = (z == 0) ? QK_SCALE2 : 1.0f;   // fold softmax scale into Q
    gemm_body(s_xhi, s_xlo, s_whi + zoff, s_wlo + zoff, oh, ol, nullptr, sc);
}
__global__ __launch_bounds__(256, 2) void gemm_out(float* __restrict__ out) {
    const size_t zoff = (size_t)3 * HIDDEN * HIDDEN;
    gemm_body(g_ohi, g_olo, s_whi + zoff, s_wlo + zoff, nullptr, nullptr, out, 1.0f);
}

// ---------------------------------------------------------------------------
// Flash attention, split-bf16, Br=128, Bc=128, 8 warps, 2 KV buffers.
// Q pre-scaled by 0.125*log2(e); softmax in exp2 domain.
// Flat grid, globally heavy-first: bx = 15 - idx/32, bh = idx % 32.
// ---------------------------------------------------------------------------
#define FQ_B   (128 * 128)              // 16384 bytes per Q matrix
#define FKV_B  (128 * 128)              // 16384 per KV matrix (128 rows x 128B)
#define OQH    0
#define OQL    FQ_B
#define OKV    (2 * FQ_B)
#define FSTAGE_B (4 * FKV_B)            // KH,KL,VH,VL = 65536
#define FSMEM  (2 * FQ_B + 2 * FSTAGE_B)   // 163840

// 128B rows, XOR swizzle on the 16B column within the row
__device__ __forceinline__ uint32_t fsw(uint32_t r, uint32_t cb) {
    return r * 128u + ((((cb >> 4) ^ r) & 7u) << 4);
}

__global__ __launch_bounds__(256) void flash_tc()
{
    extern __shared__ __align__(16) char fsm[];
    const uint32_t sb = smem_u32(fsm);

    const int tid = threadIdx.x;
    const int lane = tid & 31;
    const int wid = tid >> 5;
    const int g = lane >> 2, tig = lane & 3;
    // globally heavy-first: first 148 CTAs are the heaviest diagonal blocks
    const int idx = (int)blockIdx.x;
    const int bh = idx & 31;
    const int bx = (SEQ / 128 - 1) - (idx >> 5);      // 15 .. 0
    const int q0 = bx * 128;
    const size_t bho = (size_t)bh * SEQ * HDIM;
    const int nt = bx + 1;

    // ---- prologue loads ----
    {
        const bf16* qsrc[2] = {g_qhi + bho, g_qlo + bho};
#pragma unroll
        for (int m = 0; m < 2; m++)
#pragma unroll
            for (int i = 0; i < 4; i++) {
                int ci = tid + i * 256;            // 1024 chunks
                int r = ci >> 3, c = ci & 7;
                cp16(sb + (m ? OQL : OQH) + fsw(r, c * 16),
                     qsrc[m] + (size_t)(q0 + r) * HDIM + c * 8);
            }
    }
    auto load_kv = [&](int t, int buf) {
        const int j0 = t * 128;
        const bf16* src[4] = {g_khi + bho, g_klo + bho, g_vhi + bho, g_vlo + bho};
        uint32_t base = sb + OKV + buf * FSTAGE_B;
#pragma unroll
        for (int m = 0; m < 4; m++)
#pragma unroll
            for (int i = 0; i < 4; i++) {
                int ci = tid + i * 256;            // 1024 chunks per matrix
                int r = ci >> 3, c = ci & 7;
                cp16(base + m * FKV_B + fsw(r, c * 16),
                     src[m] + (size_t)(j0 + r) * HDIM + c * 8);
            }
    };
    load_kv(0, 0);
    CP_COMMIT();                        // group: Q + KV0
    if (nt > 1) load_kv(1, 1);
    CP_COMMIT();                        // group: KV1 (possibly empty)

    const uint32_t a_row = (uint32_t)(((lane >> 3) & 1) * 8 + (lane & 7));
    const uint32_t a_cb  = (uint32_t)((lane >> 4) * 16);
    const uint32_t b_row = (uint32_t)((lane >> 4) * 8 + (lane & 7));
    const uint32_t b_cb  = (uint32_t)(((lane >> 3) & 1) * 16);
    const uint32_t q_row = (uint32_t)(wid * 16) + a_row;

    float m0 = -1e30f, m1 = -1e30f, l0 = 0.f, l1 = 0.f;
    float o[8][4];
#pragma unroll
    for (int dt = 0; dt < 8; dt++)
#pragma unroll
        for (int e = 0; e < 4; e++) o[dt][e] = 0.f;

    for (int t = 0; t < nt; t++) {
        CP_WAIT1();
        __syncthreads();
        const uint32_t kvb = sb + OKV + (t & 1) * FSTAGE_B;

        // ---- S = Q K^T (scores already in log2 domain via pre-scaled Q) ----
        float s[16][4];
#pragma unroll
        for (int j = 0; j < 16; j++)
#pragma unroll
            for (int e = 0; e < 4; e++) s[j][e] = 0.f;
#pragma unroll
        for (int ks = 0; ks < 4; ks++) {
            const uint32_t cbq = (uint32_t)(ks * 32) + a_cb;
            uint32_t qh[4], ql[4];
            ldsm4(qh[0], qh[1], qh[2], qh[3], sb + OQH + fsw(q_row, cbq));
            ldsm4(ql[0], ql[1], ql[2], ql[3], sb + OQL + fsw(q_row, cbq));
            const uint32_t cb = (uint32_t)(ks * 32) + b_cb;
#pragma unroll
            for (int np = 0; np < 8; np++) {
                uint32_t n = (uint32_t)(np * 16) + b_row;
                uint32_t h0, h1, h2, h3, l0r, l1r, l2r, l3r;
                ldsm4(h0, h1, h2, h3, kvb + 0 * FKV_B + fsw(n, cb));
                ldsm4(l0r, l1r, l2r, l3r, kvb + 1 * FKV_B + fsw(n, cb));
                uint32_t bh0[2] = {h0, h1}, bh1[2] = {h2, h3};
                uint32_t bl0[2] = {l0r, l1r}, bl1[2] = {l2r, l3r};
                mma_bf16(s[np * 2],     qh, bh0);
                mma_bf16(s[np * 2],     qh, bl0);
                mma_bf16(s[np * 2],     ql, bh0);
                mma_bf16(s[np * 2 + 1], qh, bh1);
                mma_bf16(s[np * 2 + 1], qh, bl1);
                mma_bf16(s[np * 2 + 1], ql, bh1);
            }
        }

        // ---- causal mask (diagonal tile only; uniform branch) ----
        if (t == bx) {
            const int j0 = t * 128;
            const int r0 = q0 + wid * 16 + g;
#pragma unroll
            for (int j = 0; j < 16; j++) {
#pragma unroll
                for (int e = 0; e < 4; e++) {
                    int col = j0 + j * 8 + tig * 2 + (e & 1);
                    int row = r0 + ((e >> 1) * 8);
                    if (col > row) s[j][e] = -1e9f;
                }
            }
        }

        // ---- online softmax (rows g and g+8), exp2 domain ----
        float mx0 = -1e30f, mx1 = -1e30f;
#pragma unroll
        for (int j = 0; j < 16; j++) {
            mx0 = fmaxf(mx0, fmaxf(s[j][0], s[j][1]));
            mx1 = fmaxf(mx1, fmaxf(s[j][2], s[j][3]));
        }
        mx0 = fmaxf(mx0, __shfl_xor_sync(0xffffffffu, mx0, 1));
        mx0 = fmaxf(mx0, __shfl_xor_sync(0xffffffffu, mx0, 2));
        mx1 = fmaxf(mx1, __shfl_xor_sync(0xffffffffu, mx1, 1));
        mx1 = fmaxf(mx1, __shfl_xor_sync(0xffffffffu, mx1, 2));
        float mn0 = fmaxf(m0, mx0), mn1 = fmaxf(m1, mx1);
        float al0 = exp2f(m0 - mn0), al1 = exp2f(m1 - mn1);
        float sum0 = 0.f, sum1 = 0.f;
#pragma unroll
        for (int j = 0; j < 16; j++) {
            s[j][0] = exp2f(s[j][0] - mn0); sum0 += s[j][0];
            s[j][1] = exp2f(s[j][1] - mn0); sum0 += s[j][1];
            s[j][2] = exp2f(s[j][2] - mn1); sum1 += s[j][2];
            s[j][3] = exp2f(s[j][3] - mn1); sum1 += s[j][3];
        }
        sum0 += __shfl_xor_sync(0xffffffffu, sum0, 1);
        sum0 += __shfl_xor_sync(0xffffffffu, sum0, 2);
        sum1 += __shfl_xor_sync(0xffffffffu, sum1, 1);
        sum1 += __shfl_xor_sync(0xffffffffu, sum1, 2);
        l0 = l0 * al0 + sum0;  m0 = mn0;
        l1 = l1 * al1 + sum1;  m1 = mn1;
#pragma unroll
        for (int dt = 0; dt < 8; dt++) {
            o[dt][0] *= al0; o[dt][1] *= al0;
            o[dt][2] *= al1; o[dt][3] *= al1;
        }

        // ---- O += P V ----
#pragma unroll
        for (int kp = 0; kp < 8; kp++) {
            uint32_t ph[4], pl[4];
            hilo2(s[2 * kp][0],     s[2 * kp][1],     ph[0], pl[0]);
            hilo2(s[2 * kp][2],     s[2 * kp][3],     ph[1], pl[1]);
            hilo2(s[2 * kp + 1][0], s[2 * kp + 1][1], ph[2], pl[2]);
            hilo2(s[2 * kp + 1][2], s[2 * kp + 1][3], ph[3], pl[3]);
            uint32_t kr = (uint32_t)(kp * 16) + a_row;     // kv row within tile
#pragma unroll
            for (int np = 0; np < 4; np++) {
                uint32_t cb = (uint32_t)(np * 32) + a_cb;  // d col bytes
                uint32_t v0, v1, v2, v3, w0, w1, w2, w3;
                ldsm4t(v0, v1, v2, v3, kvb + 2 * FKV_B + fsw(kr, cb));
                ldsm4t(w0, w1, w2, w3, kvb + 3 * FKV_B + fsw(kr, cb));
                uint32_t bh0[2] = {v0, v1}, bh1[2] = {v2, v3};
                uint32_t bl0[2] = {w0, w1}, bl1[2] = {w2, w3};
                mma_bf16(o[np * 2],     ph, bh0);
                mma_bf16(o[np * 2],     ph, bl0);
                mma_bf16(o[np * 2],     pl, bh0);
                mma_bf16(o[np * 2 + 1], ph, bh1);
                mma_bf16(o[np * 2 + 1], ph, bl1);
                mma_bf16(o[np * 2 + 1], pl, bh1);
            }
        }

        __syncthreads();
        if (t + 2 < nt) load_kv(t + 2, t & 1);
        CP_COMMIT();
    }

    // ---- epilogue: O/l -> bf16 hi/lo at [b][s][h*64+d] ----
    const int b = bh >> 4, h = bh & 15;
    const int s0 = q0 + wid * 16 + g;
    const float i0 = 1.f / l0, i1 = 1.f / l1;
#pragma unroll
    for (int dt = 0; dt < 8; dt++) {
        int d = dt * 8 + tig * 2;
        size_t base0 = ((size_t)(b * SEQ) + s0) * HIDDEN + h * HDIM + d;
        size_t base1 = base0 + (size_t)8 * HIDDEN;
        uint32_t hi, lo;
        hilo2(o[dt][0] * i0, o[dt][1] * i0, hi, lo);
        *(uint32_t*)&g_ohi[base0] = hi;  *(uint32_t*)&g_olo[base0] = lo;
        hilo2(o[dt][2] * i1, o[dt][3] * i1, hi, lo);
        *(uint32_t*)&g_ohi[base1] = hi;  *(uint32_t*)&g_olo[base1] = lo;
    }
}

// ---------------------------------------------------------------------------
// Launch
// ---------------------------------------------------------------------------
extern "C" void kernel_launch(void* const* d_in, const int* in_sizes, int n_in,
                              void* d_out, int out_size)
{
    const float* X  = (const float*)d_in[0];
    // d_in[1] = attention_mask (exact causal; applied analytically)
    const float* Wq = (const float*)d_in[2];
    const float* Wk = (const float*)d_in[3];
    const float* Wv = (const float*)d_in[4];
    const float* Wo = (const float*)d_in[5];
    float* out = (float*)d_out;

    cudaFuncSetAttribute(gemm_qkv, cudaFuncAttributeMaxDynamicSharedMemorySize, GSMEM);
    cudaFuncSetAttribute(gemm_out, cudaFuncAttributeMaxDynamicSharedMemorySize, GSMEM);
    cudaFuncSetAttribute(flash_tc, cudaFuncAttributeMaxDynamicSharedMemorySize, FSMEM);

    convert_x<<<NTOK * HIDDEN / 1024, 256>>>(X);
    transpose_w<<<dim3(32, 32, 4), dim3(32, 8)>>>(Wq, Wk, Wv, Wo);

    gemm_qkv<<<dim3(HIDDEN / 128, NTOK / 128, 3), 256, GSMEM>>>();

    flash_tc<<<(SEQ / 128) * BATCH * HEADS, 256, FSMEM>>>();

    gemm_out<<<dim3(HIDDEN / 128, NTOK / 128), 256, GSMEM>>>(out);
}

// round 12
// speedup vs baseline: 1.0131x; 1.0131x over previous
#include <cuda_runtime.h>
#include <cuda_bf16.h>
#include <cstdint>

#define BATCH   2
#define SEQ     2048
#define HIDDEN  1024
#define HEADS   16
#define HDIM    64
#define NTOK    (BATCH * SEQ)          // 4096
#define QK_SCALE2 0.18033688f           // 0.125 * log2(e)

typedef __nv_bfloat16 bf16;

// ---------------------------------------------------------------------------
// Device scratch (no cudaMalloc allowed)
// ---------------------------------------------------------------------------
__device__ bf16 s_xhi[NTOK * HIDDEN];               // X split-bf16
__device__ bf16 s_xlo[NTOK * HIDDEN];
__device__ bf16 s_whi[4 * HIDDEN * HIDDEN];         // W^T split-bf16 (q,k,v,o)
__device__ bf16 s_wlo[4 * HIDDEN * HIDDEN];
__device__ bf16 g_qhi[BATCH * HEADS * SEQ * HDIM];  // [B,H,S,D] (Q pre-scaled)
__device__ bf16 g_qlo[BATCH * HEADS * SEQ * HDIM];
__device__ bf16 g_khi[BATCH * HEADS * SEQ * HDIM];
__device__ bf16 g_klo[BATCH * HEADS * SEQ * HDIM];
__device__ bf16 g_vhi[BATCH * HEADS * SEQ * HDIM];
__device__ bf16 g_vlo[BATCH * HEADS * SEQ * HDIM];
__device__ bf16 g_ohi[NTOK * HIDDEN];               // attention out [B,S,H*D]
__device__ bf16 g_olo[NTOK * HIDDEN];

// ---------------------------------------------------------------------------
// PTX helpers
// ---------------------------------------------------------------------------
__device__ __forceinline__ uint32_t smem_u32(const void* p) {
    uint32_t a;
    asm("{ .reg .u64 t; cvta.to.shared.u64 t, %1; cvt.u32.u64 %0, t; }" : "=r"(a) : "l"(p));
    return a;
}
__device__ __forceinline__ void cp16(uint32_t s, const void* g) {
    asm volatile("cp.async.cg.shared.global [%0], [%1], 16;" :: "r"(s), "l"(g) : "memory");
}
#define CP_COMMIT() asm volatile("cp.async.commit_group;" ::: "memory")
#define CP_WAIT0()  asm volatile("cp.async.wait_group 0;" ::: "memory")
#define CP_WAIT1()  asm volatile("cp.async.wait_group 1;" ::: "memory")

__device__ __forceinline__ void ldsm4(uint32_t& r0, uint32_t& r1, uint32_t& r2, uint32_t& r3, uint32_t a) {
    asm volatile("ldmatrix.sync.aligned.m8n8.x4.shared.b16 {%0,%1,%2,%3}, [%4];"
                 : "=r"(r0), "=r"(r1), "=r"(r2), "=r"(r3) : "r"(a));
}
__device__ __forceinline__ void ldsm4t(uint32_t& r0, uint32_t& r1, uint32_t& r2, uint32_t& r3, uint32_t a) {
    asm volatile("ldmatrix.sync.aligned.m8n8.x4.trans.shared.b16 {%0,%1,%2,%3}, [%4];"
                 : "=r"(r0), "=r"(r1), "=r"(r2), "=r"(r3) : "r"(a));
}
__device__ __forceinline__ void mma_bf16(float d[4], const uint32_t a[4], const uint32_t b[2]) {
    asm volatile(
        "mma.sync.aligned.m16n8k16.row.col.f32.bf16.bf16.f32 "
        "{%0,%1,%2,%3}, {%4,%5,%6,%7}, {%8,%9}, {%0,%1,%2,%3};"
        : "+f"(d[0]), "+f"(d[1]), "+f"(d[2]), "+f"(d[3])
        : "r"(a[0]), "r"(a[1]), "r"(a[2]), "r"(a[3]), "r"(b[0]), "r"(b[1]));
}
// split x,y into packed bf16 hi pair + lo pair (packed cvt)
__device__ __forceinline__ void hilo2(float x, float y, uint32_t& hi, uint32_t& lo) {
    __nv_bfloat162 h2 = __floats2bfloat162_rn(x, y);   // x->low, y->high
    float rx = x - __bfloat162float(h2.x);
    float ry = y - __bfloat162float(h2.y);
    __nv_bfloat162 l2 = __floats2bfloat162_rn(rx, ry);
    hi = *reinterpret_cast<uint32_t*>(&h2);
    lo = *reinterpret_cast<uint32_t*>(&l2);
}

// ---------------------------------------------------------------------------
// Pre-convert kernels
// ---------------------------------------------------------------------------
__global__ __launch_bounds__(256) void convert_x(const float* __restrict__ X) {
    size_t i4 = ((size_t)blockIdx.x * 256 + threadIdx.x) * 4;
    float4 v = *(const float4*)&X[i4];
    uint32_t h0, l0, h1, l1;
    hilo2(v.x, v.y, h0, l0);
    hilo2(v.z, v.w, h1, l1);
    *(uint32_t*)&s_xhi[i4]     = h0;  *(uint32_t*)&s_xhi[i4 + 2] = h1;
    *(uint32_t*)&s_xlo[i4]     = l0;  *(uint32_t*)&s_xlo[i4 + 2] = l1;
}

// W [k][n] -> Wt [n][k] split-bf16, 32x32 tiles
__global__ __launch_bounds__(256) void transpose_w(
    const float* __restrict__ w0, const float* __restrict__ w1,
    const float* __restrict__ w2, const float* __restrict__ w3)
{
    __shared__ float t[32][33];
    const int z = blockIdx.z;
    const float* W = (z == 0) ? w0 : (z == 1) ? w1 : (z == 2) ? w2 : w3;
    const size_t zoff = (size_t)z * HIDDEN * HIDDEN;
    const int n0 = blockIdx.x * 32, k0 = blockIdx.y * 32;
    const int tx = threadIdx.x, ty = threadIdx.y;   // 32 x 8
#pragma unroll
    for (int i = 0; i < 4; i++)
        t[ty + i * 8][tx] = W[(size_t)(k0 + ty + i * 8) * HIDDEN + n0 + tx];
    __syncthreads();
#pragma unroll
    for (int i = 0; i < 4; i++) {
        int nr = ty + i * 8;
        float v = t[tx][nr];
        bf16 h = __float2bfloat16_rn(v);
        bf16 l = __float2bfloat16_rn(v - __bfloat162float(h));
        s_whi[zoff + (size_t)(n0 + nr) * HIDDEN + k0 + tx] = h;
        s_wlo[zoff + (size_t)(n0 + nr) * HIDDEN + k0 + tx] = l;
    }
}

// ---------------------------------------------------------------------------
// Split-bf16 GEMM: C[4096x1024] = A @ Wt^T ; A,Wt row-major bf16 hi/lo.
// Block 128x128xBK32, 2-stage cp.async, 8 warps (warp tile 64x32), 2 CTAs/SM.
// MMA issue is term-major: same-accumulator distance 8 (RAW-chain free).
// ---------------------------------------------------------------------------
#define GBK     32
#define GKITERS (HIDDEN / GBK)          // 32
#define GSTR    80                      // bytes per smem row (40 bf16, pad)
#define GT_B    (128 * GSTR)            // 10240 per matrix tile
#define OA_HI   0
#define OA_LO   GT_B
#define OB_HI   (2 * GT_B)
#define OB_LO   (3 * GT_B)
#define GSTAGE_B (4 * GT_B)             // 40960
#define GSMEM   (2 * GSTAGE_B)          // 81920 (x2 CTAs = 160K)

__device__ __forceinline__ void gemm_load_stage(
    uint32_t sb, const bf16* __restrict__ Ahi, const bf16* __restrict__ Alo,
    const bf16* __restrict__ Bhi, const bf16* __restrict__ Blo,
    int row0, int col0, int kc, int tid)
{
    const int k0 = kc * GBK;
#pragma unroll
    for (int i = 0; i < 2; i++) {
        int idx = tid + i * 256;        // 512 chunks per matrix
        int r = idx >> 2, c = idx & 3;  // r 0..127, c 0..3 (16B chunks)
        uint32_t so = (uint32_t)(r * GSTR + c * 16);
        size_t ga = (size_t)(row0 + r) * HIDDEN + k0 + c * 8;
        size_t gb = (size_t)(col0 + r) * HIDDEN + k0 + c * 8;
        cp16(sb + OA_HI + so, &Ahi[ga]);
        cp16(sb + OA_LO + so, &Alo[ga]);
        cp16(sb + OB_HI + so, &Bhi[gb]);
        cp16(sb + OB_LO + so, &Blo[gb]);
    }
}

__device__ __forceinline__ void gemm_body(
    const bf16* __restrict__ Ahi, const bf16* __restrict__ Alo,
    const bf16* __restrict__ Bhi, const bf16* __restrict__ Blo,
    bf16* __restrict__ OutHi, bf16* __restrict__ OutLo,   // mode qkv (permuted)
    float* __restrict__ OutF,                             // mode fp32 row-major
    float oscale)
{
    extern __shared__ __align__(16) char gsm[];
    const uint32_t sb0 = smem_u32(gsm);

    const int tid = threadIdx.x;        // 256 threads
    const int lane = tid & 31;
    const int wid = tid >> 5;           // 0..7
    const int g = lane >> 2, tig = lane & 3;
    const int warp_m = wid >> 2;        // 0..1 (64 rows)
    const int warp_n = wid & 3;         // 0..3 (32 cols)
    const int row0 = blockIdx.y * 128;
    const int col0 = blockIdx.x * 128;

    float acc[4][4][4];
#pragma unroll
    for (int mi = 0; mi < 4; mi++)
#pragma unroll
        for (int ni = 0; ni < 4; ni++)
#pragma unroll
            for (int e = 0; e < 4; e++) acc[mi][ni][e] = 0.f;

    gemm_load_stage(sb0, Ahi, Alo, Bhi, Blo, row0, col0, 0, tid);
    CP_COMMIT();

    const uint32_t a_row = (uint32_t)(((lane >> 3) & 1) * 8 + (lane & 7));
    const uint32_t a_cb  = (uint32_t)((lane >> 4) * 16);
    const uint32_t b_row = (uint32_t)((lane >> 4) * 8 + (lane & 7));
    const uint32_t b_cb  = (uint32_t)(((lane >> 3) & 1) * 16);

    for (int kc = 0; kc < GKITERS; kc++) {
        CP_WAIT0();
        __syncthreads();
        if (kc + 1 < GKITERS)
            gemm_load_stage(sb0 + ((kc + 1) & 1) * GSTAGE_B, Ahi, Alo, Bhi, Blo,
                            row0, col0, kc + 1, tid);
        CP_COMMIT();

        const uint32_t sb = sb0 + (kc & 1) * GSTAGE_B;
#pragma unroll
        for (int ks = 0; ks < 2; ks++) {           // two k16 slices
            const uint32_t cbA = (uint32_t)(ks * 32) + a_cb;
            const uint32_t cbB = (uint32_t)(ks * 32) + b_cb;
            uint32_t ah[4][4], al[4][4];
#pragma unroll
            for (int mi = 0; mi < 4; mi++) {
                uint32_t r = (uint32_t)(warp_m * 64 + mi * 16) + a_row;
                uint32_t ad = sb + r * GSTR + cbA;
                ldsm4(ah[mi][0], ah[mi][1], ah[mi][2], ah[mi][3], ad + OA_HI);
                ldsm4(al[mi][0], al[mi][1], al[mi][2], al[mi][3], ad + OA_LO);
            }
#pragma unroll
            for (int np = 0; np < 2; np++) {       // n16 pairs (32 cols)
                uint32_t n = (uint32_t)(warp_n * 32 + np * 16) + b_row;
                uint32_t bd = sb + n * GSTR + cbB;
                uint32_t h0, h1, h2, h3, l0, l1, l2, l3;
                ldsm4(h0, h1, h2, h3, bd + OB_HI);
                ldsm4(l0, l1, l2, l3, bd + OB_LO);
                uint32_t bh0[2] = {h0, h1}, bh1[2] = {h2, h3};
                uint32_t bl0[2] = {l0, l1}, bl1[2] = {l2, l3};
                // term-major: same-acc distance 8
#pragma unroll
                for (int mi = 0; mi < 4; mi++) {
                    mma_bf16(acc[mi][np * 2],     ah[mi], bh0);
                    mma_bf16(acc[mi][np * 2 + 1], ah[mi], bh1);
                }
#pragma unroll
                for (int mi = 0; mi < 4; mi++) {
                    mma_bf16(acc[mi][np * 2],     ah[mi], bl0);
                    mma_bf16(acc[mi][np * 2 + 1], ah[mi], bl1);
                }
#pragma unroll
                for (int mi = 0; mi < 4; mi++) {
                    mma_bf16(acc[mi][np * 2],     al[mi], bh0);
                    mma_bf16(acc[mi][np * 2 + 1], al[mi], bh1);
                }
            }
        }
    }

    // epilogue
#pragma unroll
    for (int mi = 0; mi < 4; mi++) {
        int r = row0 + warp_m * 64 + mi * 16 + g;       // rows r, r+8
#pragma unroll
        for (int ni = 0; ni < 4; ni++) {
            int col = col0 + warp_n * 32 + ni * 8 + tig * 2;
            if (OutF) {
                *(float2*)&OutF[(size_t)r * HIDDEN + col] =
                    make_float2(acc[mi][ni][0], acc[mi][ni][1]);
                *(float2*)&OutF[(size_t)(r + 8) * HIDDEN + col] =
                    make_float2(acc[mi][ni][2], acc[mi][ni][3]);
            } else {
                int h = col >> 6, d = col & 63;
                int b0 = r >> 11, s0 = r & 2047;
                int b1 = (r + 8) >> 11, s1 = (r + 8) & 2047;
                size_t i0 = (((size_t)(b0 * HEADS + h)) * SEQ + s0) * HDIM + d;
                size_t i1 = (((size_t)(b1 * HEADS + h)) * SEQ + s1) * HDIM + d;
                uint32_t hi, lo;
                hilo2(acc[mi][ni][0] * oscale, acc[mi][ni][1] * oscale, hi, lo);
                *(uint32_t*)&OutHi[i0] = hi;  *(uint32_t*)&OutLo[i0] = lo;
                hilo2(acc[mi][ni][2] * oscale, acc[mi][ni][3] * oscale, hi, lo);
                *(uint32_t*)&OutHi[i1] = hi;  *(uint32_t*)&OutLo[i1] = lo;
            }
        }
    }
}

__global__ __launch_bounds__(256, 2) void gemm_qkv() {
    const int z = blockIdx.z;
    const size_t zoff = (size_t)z * HIDDEN * HIDDEN;
    bf16* oh = (z == 0) ? g_qhi : (z == 1) ? g_khi : g_vhi;
    bf16* ol = (z == 0) ? g_qlo : (z == 1) ? g_klo : g_vlo;
    float sc = (z == 0) ? QK_SCALE2 : 1.0f;   // fold softmax scale into Q
    gemm_body(s_xhi, s_xlo, s_whi + zoff, s_wlo + zoff, oh, ol, nullptr, sc);
}
__global__ __launch_bounds__(256, 2) void gemm_out(float* __restrict__ out) {
    const size_t zoff = (size_t)3 * HIDDEN * HIDDEN;
    gemm_body(g_ohi, g_olo, s_whi + zoff, s_wlo + zoff, nullptr, nullptr, out, 1.0f);
}

// ---------------------------------------------------------------------------
// Flash attention, split-bf16, Br=128, Bc=128, 8 warps, 2 KV buffers.
// Q pre-scaled by 0.125*log2(e); softmax in exp2 domain.
// Flat grid, globally heavy-first. MMA issue term-major (same-acc distance 4).
// ---------------------------------------------------------------------------
#define FQ_B   (128 * 128)              // 16384 bytes per Q matrix
#define FKV_B  (128 * 128)              // 16384 per KV matrix (128 rows x 128B)
#define OQH    0
#define OQL    FQ_B
#define OKV    (2 * FQ_B)
#define FSTAGE_B (4 * FKV_B)            // KH,KL,VH,VL = 65536
#define FSMEM  (2 * FQ_B + 2 * FSTAGE_B)   // 163840

// 128B rows, XOR swizzle on the 16B column within the row
__device__ __forceinline__ uint32_t fsw(uint32_t r, uint32_t cb) {
    return r * 128u + ((((cb >> 4) ^ r) & 7u) << 4);
}

__global__ __launch_bounds__(256) void flash_tc()
{
    extern __shared__ __align__(16) char fsm[];
    const uint32_t sb = smem_u32(fsm);

    const int tid = threadIdx.x;
    const int lane = tid & 31;
    const int wid = tid >> 5;
    const int g = lane >> 2, tig = lane & 3;
    // globally heavy-first: first 148 CTAs are the heaviest diagonal blocks
    const int idx = (int)blockIdx.x;
    const int bh = idx & 31;
    const int bx = (SEQ / 128 - 1) - (idx >> 5);      // 15 .. 0
    const int q0 = bx * 128;
    const size_t bho = (size_t)bh * SEQ * HDIM;
    const int nt = bx + 1;

    // ---- prologue loads ----
    {
        const bf16* qsrc[2] = {g_qhi + bho, g_qlo + bho};
#pragma unroll
        for (int m = 0; m < 2; m++)
#pragma unroll
            for (int i = 0; i < 4; i++) {
                int ci = tid + i * 256;            // 1024 chunks
                int r = ci >> 3, c = ci & 7;
                cp16(sb + (m ? OQL : OQH) + fsw(r, c * 16),
                     qsrc[m] + (size_t)(q0 + r) * HDIM + c * 8);
            }
    }
    auto load_kv = [&](int t, int buf) {
        const int j0 = t * 128;
        const bf16* src[4] = {g_khi + bho, g_klo + bho, g_vhi + bho, g_vlo + bho};
        uint32_t base = sb + OKV + buf * FSTAGE_B;
#pragma unroll
        for (int m = 0; m < 4; m++)
#pragma unroll
            for (int i = 0; i < 4; i++) {
                int ci = tid + i * 256;            // 1024 chunks per matrix
                int r = ci >> 3, c = ci & 7;
                cp16(base + m * FKV_B + fsw(r, c * 16),
                     src[m] + (size_t)(j0 + r) * HDIM + c * 8);
            }
    };
    load_kv(0, 0);
    CP_COMMIT();                        // group: Q + KV0
    if (nt > 1) load_kv(1, 1);
    CP_COMMIT();                        // group: KV1 (possibly empty)

    const uint32_t a_row = (uint32_t)(((lane >> 3) & 1) * 8 + (lane & 7));
    const uint32_t a_cb  = (uint32_t)((lane >> 4) * 16);
    const uint32_t b_row = (uint32_t)((lane >> 4) * 8 + (lane & 7));
    const uint32_t b_cb  = (uint32_t)(((lane >> 3) & 1) * 16);
    const uint32_t q_row = (uint32_t)(wid * 16) + a_row;

    float m0 = -1e30f, m1 = -1e30f, l0 = 0.f, l1 = 0.f;
    float o[8][4];
#pragma unroll
    for (int dt = 0; dt < 8; dt++)
#pragma unroll
        for (int e = 0; e < 4; e++) o[dt][e] = 0.f;

    for (int t = 0; t < nt; t++) {
        CP_WAIT1();
        __syncthreads();
        const uint32_t kvb = sb + OKV + (t & 1) * FSTAGE_B;

        // ---- S = Q K^T (scores already in log2 domain via pre-scaled Q) ----
        float s[16][4];
#pragma unroll
        for (int j = 0; j < 16; j++)
#pragma unroll
            for (int e = 0; e < 4; e++) s[j][e] = 0.f;
#pragma unroll
        for (int ks = 0; ks < 4; ks++) {
            const uint32_t cbq = (uint32_t)(ks * 32) + a_cb;
            uint32_t qh[4], ql[4];
            ldsm4(qh[0], qh[1], qh[2], qh[3], sb + OQH + fsw(q_row, cbq));
            ldsm4(ql[0], ql[1], ql[2], ql[3], sb + OQL + fsw(q_row, cbq));
            const uint32_t cb = (uint32_t)(ks * 32) + b_cb;
#pragma unroll
            for (int npp = 0; npp < 4; npp++) {    // pairs of n16 groups
                uint32_t kh[4][2], kl[4][2];
#pragma unroll
                for (int q = 0; q < 2; q++) {
                    uint32_t n = (uint32_t)((npp * 2 + q) * 16) + b_row;
                    uint32_t h0, h1, h2, h3, l0r, l1r, l2r, l3r;
                    ldsm4(h0, h1, h2, h3, kvb + 0 * FKV_B + fsw(n, cb));
                    ldsm4(l0r, l1r, l2r, l3r, kvb + 1 * FKV_B + fsw(n, cb));
                    kh[q * 2][0] = h0;  kh[q * 2][1] = h1;
                    kh[q * 2 + 1][0] = h2;  kh[q * 2 + 1][1] = h3;
                    kl[q * 2][0] = l0r;  kl[q * 2][1] = l1r;
                    kl[q * 2 + 1][0] = l2r;  kl[q * 2 + 1][1] = l3r;
                }
                // term-major: same-acc distance 4
#pragma unroll
                for (int a = 0; a < 4; a++) mma_bf16(s[npp * 4 + a], qh, kh[a]);
#pragma unroll
                for (int a = 0; a < 4; a++) mma_bf16(s[npp * 4 + a], qh, kl[a]);
#pragma unroll
                for (int a = 0; a < 4; a++) mma_bf16(s[npp * 4 + a], ql, kh[a]);
            }
        }

        // ---- causal mask (diagonal tile only; uniform branch) ----
        if (t == bx) {
            const int j0 = t * 128;
            const int r0 = q0 + wid * 16 + g;
#pragma unroll
            for (int j = 0; j < 16; j++) {
#pragma unroll
                for (int e = 0; e < 4; e++) {
                    int col = j0 + j * 8 + tig * 2 + (e & 1);
                    int row = r0 + ((e >> 1) * 8);
                    if (col > row) s[j][e] = -1e9f;
                }
            }
        }

        // ---- online softmax (rows g and g+8), exp2 domain ----
        float mx0 = -1e30f, mx1 = -1e30f;
#pragma unroll
        for (int j = 0; j < 16; j++) {
            mx0 = fmaxf(mx0, fmaxf(s[j][0], s[j][1]));
            mx1 = fmaxf(mx1, fmaxf(s[j][2], s[j][3]));
        }
        mx0 = fmaxf(mx0, __shfl_xor_sync(0xffffffffu, mx0, 1));
        mx0 = fmaxf(mx0, __shfl_xor_sync(0xffffffffu, mx0, 2));
        mx1 = fmaxf(mx1, __shfl_xor_sync(0xffffffffu, mx1, 1));
        mx1 = fmaxf(mx1, __shfl_xor_sync(0xffffffffu, mx1, 2));
        float mn0 = fmaxf(m0, mx0), mn1 = fmaxf(m1, mx1);
        float al0 = exp2f(m0 - mn0), al1 = exp2f(m1 - mn1);
        float sum0 = 0.f, sum1 = 0.f;
#pragma unroll
        for (int j = 0; j < 16; j++) {
            s[j][0] = exp2f(s[j][0] - mn0); sum0 += s[j][0];
            s[j][1] = exp2f(s[j][1] - mn0); sum0 += s[j][1];
            s[j][2] = exp2f(s[j][2] - mn1); sum1 += s[j][2];
            s[j][3] = exp2f(s[j][3] - mn1); sum1 += s[j][3];
        }
        sum0 += __shfl_xor_sync(0xffffffffu, sum0, 1);
        sum0 += __shfl_xor_sync(0xffffffffu, sum0, 2);
        sum1 += __shfl_xor_sync(0xffffffffu, sum1, 1);
        sum1 += __shfl_xor_sync(0xffffffffu, sum1, 2);
        l0 = l0 * al0 + sum0;  m0 = mn0;
        l1 = l1 * al1 + sum1;  m1 = mn1;
#pragma unroll
        for (int dt = 0; dt < 8; dt++) {
            o[dt][0] *= al0; o[dt][1] *= al0;
            o[dt][2] *= al1; o[dt][3] *= al1;
        }

        // ---- O += P V (term-major pairs: same-acc distance 4) ----
#pragma unroll
        for (int kp = 0; kp < 8; kp++) {
            uint32_t ph[4], pl[4];
            hilo2(s[2 * kp][0],     s[2 * kp][1],     ph[0], pl[0]);
            hilo2(s[2 * kp][2],     s[2 * kp][3],     ph[1], pl[1]);
            hilo2(s[2 * kp + 1][0], s[2 * kp + 1][1], ph[2], pl[2]);
            hilo2(s[2 * kp + 1][2], s[2 * kp + 1][3], ph[3], pl[3]);
            uint32_t kr = (uint32_t)(kp * 16) + a_row;     // kv row within tile
#pragma unroll
            for (int npp = 0; npp < 2; npp++) {
                uint32_t vh[4][2], vl[4][2];
#pragma unroll
                for (int q = 0; q < 2; q++) {
                    uint32_t cb = (uint32_t)((npp * 2 + q) * 32) + a_cb;
                    uint32_t v0, v1, v2, v3, w0, w1, w2, w3;
                    ldsm4t(v0, v1, v2, v3, kvb + 2 * FKV_B + fsw(kr, cb));
                    ldsm4t(w0, w1, w2, w3, kvb + 3 * FKV_B + fsw(kr, cb));
                    vh[q * 2][0] = v0;  vh[q * 2][1] = v1;
                    vh[q * 2 + 1][0] = v2;  vh[q * 2 + 1][1] = v3;
                    vl[q * 2][0] = w0;  vl[q * 2][1] = w1;
                    vl[q * 2 + 1][0] = w2;  vl[q * 2 + 1][1] = w3;
                }
#pragma unroll
                for (int a = 0; a < 4; a++) mma_bf16(o[npp * 4 + a], ph, vh[a]);
#pragma unroll
                for (int a = 0; a < 4; a++) mma_bf16(o[npp * 4 + a], ph, vl[a]);
#pragma unroll
                for (int a = 0; a < 4; a++) mma_bf16(o[npp * 4 + a], pl, vh[a]);
            }
        }

        __syncthreads();
        if (t + 2 < nt) load_kv(t + 2, t & 1);
        CP_COMMIT();
    }

    // ---- epilogue: O/l -> bf16 hi/lo at [b][s][h*64+d] ----
    const int b = bh >> 4, h = bh & 15;
    const int s0 = q0 + wid * 16 + g;
    const float i0 = 1.f / l0, i1 = 1.f / l1;
#pragma unroll
    for (int dt = 0; dt < 8; dt++) {
        int d = dt * 8 + tig * 2;
        size_t base0 = ((size_t)(b * SEQ) + s0) * HIDDEN + h * HDIM + d;
        size_t base1 = base0 + (size_t)8 * HIDDEN;
        uint32_t hi, lo;
        hilo2(o[dt][0] * i0, o[dt][1] * i0, hi, lo);
        *(uint32_t*)&g_ohi[base0] = hi;  *(uint32_t*)&g_olo[base0] = lo;
        hilo2(o[dt][2] * i1, o[dt][3] * i1, hi, lo);
        *(uint32_t*)&g_ohi[base1] = hi;  *(uint32_t*)&g_olo[base1] = lo;
    }
}

// ---------------------------------------------------------------------------
// Launch
// ---------------------------------------------------------------------------
extern "C" void kernel_launch(void* const* d_in, const int* in_sizes, int n_in,
                              void* d_out, int out_size)
{
    const float* X  = (const float*)d_in[0];
    // d_in[1] = attention_mask (exact causal; applied analytically)
    const float* Wq = (const float*)d_in[2];
    const float* Wk = (const float*)d_in[3];
    const float* Wv = (const float*)d_in[4];
    const float* Wo = (const float*)d_in[5];
    float* out = (float*)d_out;

    cudaFuncSetAttribute(gemm_qkv, cudaFuncAttributeMaxDynamicSharedMemorySize, GSMEM);
    cudaFuncSetAttribute(gemm_out, cudaFuncAttributeMaxDynamicSharedMemorySize, GSMEM);
    cudaFuncSetAttribute(flash_tc, cudaFuncAttributeMaxDynamicSharedMemorySize, FSMEM);

    convert_x<<<NTOK * HIDDEN / 1024, 256>>>(X);
    transpose_w<<<dim3(32, 32, 4), dim3(32, 8)>>>(Wq, Wk, Wv, Wo);

    gemm_qkv<<<dim3(HIDDEN / 128, NTOK / 128, 3), 256, GSMEM>>>();

    flash_tc<<<(SEQ / 128) * BATCH * HEADS, 256, FSMEM>>>();

    gemm_out<<<dim3(HIDDEN / 128, NTOK / 128), 256, GSMEM>>>(out);
}

// round 13
// speedup vs baseline: 1.0132x; 1.0001x over previous
#include <cuda_runtime.h>
#include <cuda_bf16.h>
#include <cstdint>

#define BATCH   2
#define SEQ     2048
#define HIDDEN  1024
#define HEADS   16
#define HDIM    64
#define NTOK    (BATCH * SEQ)          // 4096
#define QK_SCALE2 0.18033688f           // 0.125 * log2(e)

typedef __nv_bfloat16 bf16;

// ---------------------------------------------------------------------------
// Device scratch (no cudaMalloc allowed)
// ---------------------------------------------------------------------------
__device__ bf16 s_xhi[NTOK * HIDDEN];               // X split-bf16
__device__ bf16 s_xlo[NTOK * HIDDEN];
__device__ bf16 s_whi[4 * HIDDEN * HIDDEN];         // W^T split-bf16 (q,k,v,o)
__device__ bf16 s_wlo[4 * HIDDEN * HIDDEN];
__device__ bf16 g_qhi[BATCH * HEADS * SEQ * HDIM];  // [B,H,S,D] (Q pre-scaled)
__device__ bf16 g_qlo[BATCH * HEADS * SEQ * HDIM];
__device__ bf16 g_khi[BATCH * HEADS * SEQ * HDIM];
__device__ bf16 g_klo[BATCH * HEADS * SEQ * HDIM];
__device__ bf16 g_vhi[BATCH * HEADS * SEQ * HDIM];
__device__ bf16 g_vlo[BATCH * HEADS * SEQ * HDIM];
__device__ bf16 g_ohi[NTOK * HIDDEN];               // attention out [B,S,H*D]
__device__ bf16 g_olo[NTOK * HIDDEN];

// ---------------------------------------------------------------------------
// PTX helpers
// ---------------------------------------------------------------------------
__device__ __forceinline__ uint32_t smem_u32(const void* p) {
    uint32_t a;
    asm("{ .reg .u64 t; cvta.to.shared.u64 t, %1; cvt.u32.u64 %0, t; }" : "=r"(a) : "l"(p));
    return a;
}
__device__ __forceinline__ void cp16(uint32_t s, const void* g) {
    asm volatile("cp.async.cg.shared.global [%0], [%1], 16;" :: "r"(s), "l"(g) : "memory");
}
#define CP_COMMIT() asm volatile("cp.async.commit_group;" ::: "memory")
#define CP_WAIT0()  asm volatile("cp.async.wait_group 0;" ::: "memory")
#define CP_WAIT1()  asm volatile("cp.async.wait_group 1;" ::: "memory")

__device__ __forceinline__ void ldsm4(uint32_t& r0, uint32_t& r1, uint32_t& r2, uint32_t& r3, uint32_t a) {
    asm volatile("ldmatrix.sync.aligned.m8n8.x4.shared.b16 {%0,%1,%2,%3}, [%4];"
                 : "=r"(r0), "=r"(r1), "=r"(r2), "=r"(r3) : "r"(a));
}
__device__ __forceinline__ void ldsm4t(uint32_t& r0, uint32_t& r1, uint32_t& r2, uint32_t& r3, uint32_t a) {
    asm volatile("ldmatrix.sync.aligned.m8n8.x4.trans.shared.b16 {%0,%1,%2,%3}, [%4];"
                 : "=r"(r0), "=r"(r1), "=r"(r2), "=r"(r3) : "r"(a));
}
__device__ __forceinline__ void mma_bf16(float d[4], const uint32_t a[4], const uint32_t b[2]) {
    asm volatile(
        "mma.sync.aligned.m16n8k16.row.col.f32.bf16.bf16.f32 "
        "{%0,%1,%2,%3}, {%4,%5,%6,%7}, {%8,%9}, {%0,%1,%2,%3};"
        : "+f"(d[0]), "+f"(d[1]), "+f"(d[2]), "+f"(d[3])
        : "r"(a[0]), "r"(a[1]), "r"(a[2]), "r"(a[3]), "r"(b[0]), "r"(b[1]));
}
// split x,y into packed bf16 hi pair + lo pair (packed cvt)
__device__ __forceinline__ void hilo2(float x, float y, uint32_t& hi, uint32_t& lo) {
    __nv_bfloat162 h2 = __floats2bfloat162_rn(x, y);   // x->low, y->high
    float rx = x - __bfloat162float(h2.x);
    float ry = y - __bfloat162float(h2.y);
    __nv_bfloat162 l2 = __floats2bfloat162_rn(rx, ry);
    hi = *reinterpret_cast<uint32_t*>(&h2);
    lo = *reinterpret_cast<uint32_t*>(&l2);
}

// ---------------------------------------------------------------------------
// Pre-convert kernels
// ---------------------------------------------------------------------------
__global__ __launch_bounds__(256) void convert_x(const float* __restrict__ X) {
    size_t i4 = ((size_t)blockIdx.x * 256 + threadIdx.x) * 4;
    float4 v = *(const float4*)&X[i4];
    uint32_t h0, l0, h1, l1;
    hilo2(v.x, v.y, h0, l0);
    hilo2(v.z, v.w, h1, l1);
    *(uint32_t*)&s_xhi[i4]     = h0;  *(uint32_t*)&s_xhi[i4 + 2] = h1;
    *(uint32_t*)&s_xlo[i4]     = l0;  *(uint32_t*)&s_xlo[i4 + 2] = l1;
}

// W [k][n] -> Wt [n][k] split-bf16, 32x32 tiles
__global__ __launch_bounds__(256) void transpose_w(
    const float* __restrict__ w0, const float* __restrict__ w1,
    const float* __restrict__ w2, const float* __restrict__ w3)
{
    __shared__ float t[32][33];
    const int z = blockIdx.z;
    const float* W = (z == 0) ? w0 : (z == 1) ? w1 : (z == 2) ? w2 : w3;
    const size_t zoff = (size_t)z * HIDDEN * HIDDEN;
    const int n0 = blockIdx.x * 32, k0 = blockIdx.y * 32;
    const int tx = threadIdx.x, ty = threadIdx.y;   // 32 x 8
#pragma unroll
    for (int i = 0; i < 4; i++)
        t[ty + i * 8][tx] = W[(size_t)(k0 + ty + i * 8) * HIDDEN + n0 + tx];
    __syncthreads();
#pragma unroll
    for (int i = 0; i < 4; i++) {
        int nr = ty + i * 8;
        float v = t[tx][nr];
        bf16 h = __float2bfloat16_rn(v);
        bf16 l = __float2bfloat16_rn(v - __bfloat162float(h));
        s_whi[zoff + (size_t)(n0 + nr) * HIDDEN + k0 + tx] = h;
        s_wlo[zoff + (size_t)(n0 + nr) * HIDDEN + k0 + tx] = l;
    }
}

// ---------------------------------------------------------------------------
// Split-bf16 GEMM: C[4096x1024] = A @ Wt^T ; A,Wt row-major bf16 hi/lo.
// Block 128x128xBK32, 2-stage cp.async, 8 warps (warp tile 64x32), 2 CTAs/SM.
// ---------------------------------------------------------------------------
#define GBK     32
#define GKITERS (HIDDEN / GBK)          // 32
#define GSTR    80                      // bytes per smem row (40 bf16, pad)
#define GT_B    (128 * GSTR)            // 10240 per matrix tile
#define OA_HI   0
#define OA_LO   GT_B
#define OB_HI   (2 * GT_B)
#define OB_LO   (3 * GT_B)
#define GSTAGE_B (4 * GT_B)             // 40960
#define GSMEM   (2 * GSTAGE_B)          // 81920 (x2 CTAs = 160K)

__device__ __forceinline__ void gemm_load_stage(
    uint32_t sb, const bf16* __restrict__ Ahi, const bf16* __restrict__ Alo,
    const bf16* __restrict__ Bhi, const bf16* __restrict__ Blo,
    int row0, int col0, int kc, int tid)
{
    const int k0 = kc * GBK;
#pragma unroll
    for (int i = 0; i < 2; i++) {
        int idx = tid + i * 256;        // 512 chunks per matrix
        int r = idx >> 2, c = idx & 3;  // r 0..127, c 0..3 (16B chunks)
        uint32_t so = (uint32_t)(r * GSTR + c * 16);
        size_t ga = (size_t)(row0 + r) * HIDDEN + k0 + c * 8;
        size_t gb = (size_t)(col0 + r) * HIDDEN + k0 + c * 8;
        cp16(sb + OA_HI + so, &Ahi[ga]);
        cp16(sb + OA_LO + so, &Alo[ga]);
        cp16(sb + OB_HI + so, &Bhi[gb]);
        cp16(sb + OB_LO + so, &Blo[gb]);
    }
}

__device__ __forceinline__ void gemm_body(
    const bf16* __restrict__ Ahi, const bf16* __restrict__ Alo,
    const bf16* __restrict__ Bhi, const bf16* __restrict__ Blo,
    bf16* __restrict__ OutHi, bf16* __restrict__ OutLo,   // mode qkv (permuted)
    float* __restrict__ OutF,                             // mode fp32 row-major
    float oscale)
{
    extern __shared__ __align__(16) char gsm[];
    const uint32_t sb0 = smem_u32(gsm);

    const int tid = threadIdx.x;        // 256 threads
    const int lane = tid & 31;
    const int wid = tid >> 5;           // 0..7
    const int g = lane >> 2, tig = lane & 3;
    const int warp_m = wid >> 2;        // 0..1 (64 rows)
    const int warp_n = wid & 3;         // 0..3 (32 cols)
    const int row0 = blockIdx.y * 128;
    const int col0 = blockIdx.x * 128;

    float acc[4][4][4];
#pragma unroll
    for (int mi = 0; mi < 4; mi++)
#pragma unroll
        for (int ni = 0; ni < 4; ni++)
#pragma unroll
            for (int e = 0; e < 4; e++) acc[mi][ni][e] = 0.f;

    gemm_load_stage(sb0, Ahi, Alo, Bhi, Blo, row0, col0, 0, tid);
    CP_COMMIT();

    const uint32_t a_row = (uint32_t)(((lane >> 3) & 1) * 8 + (lane & 7));
    const uint32_t a_cb  = (uint32_t)((lane >> 4) * 16);
    const uint32_t b_row = (uint32_t)((lane >> 4) * 8 + (lane & 7));
    const uint32_t b_cb  = (uint32_t)(((lane >> 3) & 1) * 16);

    for (int kc = 0; kc < GKITERS; kc++) {
        CP_WAIT0();
        __syncthreads();
        if (kc + 1 < GKITERS)
            gemm_load_stage(sb0 + ((kc + 1) & 1) * GSTAGE_B, Ahi, Alo, Bhi, Blo,
                            row0, col0, kc + 1, tid);
        CP_COMMIT();

        const uint32_t sb = sb0 + (kc & 1) * GSTAGE_B;
#pragma unroll
        for (int ks = 0; ks < 2; ks++) {           // two k16 slices
            const uint32_t cbA = (uint32_t)(ks * 32) + a_cb;
            const uint32_t cbB = (uint32_t)(ks * 32) + b_cb;
            uint32_t ah[4][4], al[4][4];
#pragma unroll
            for (int mi = 0; mi < 4; mi++) {
                uint32_t r = (uint32_t)(warp_m * 64 + mi * 16) + a_row;
                uint32_t ad = sb + r * GSTR + cbA;
                ldsm4(ah[mi][0], ah[mi][1], ah[mi][2], ah[mi][3], ad + OA_HI);
                ldsm4(al[mi][0], al[mi][1], al[mi][2], al[mi][3], ad + OA_LO);
            }
#pragma unroll
            for (int np = 0; np < 2; np++) {       // n16 pairs (32 cols)
                uint32_t n = (uint32_t)(warp_n * 32 + np * 16) + b_row;
                uint32_t bd = sb + n * GSTR + cbB;
                uint32_t h0, h1, h2, h3, l0, l1, l2, l3;
                ldsm4(h0, h1, h2, h3, bd + OB_HI);
                ldsm4(l0, l1, l2, l3, bd + OB_LO);
                uint32_t bh0[2] = {h0, h1}, bh1[2] = {h2, h3};
                uint32_t bl0[2] = {l0, l1}, bl1[2] = {l2, l3};
#pragma unroll
                for (int mi = 0; mi < 4; mi++) {
                    mma_bf16(acc[mi][np * 2],     ah[mi], bh0);
                    mma_bf16(acc[mi][np * 2 + 1], ah[mi], bh1);
                }
#pragma unroll
                for (int mi = 0; mi < 4; mi++) {
                    mma_bf16(acc[mi][np * 2],     ah[mi], bl0);
                    mma_bf16(acc[mi][np * 2 + 1], ah[mi], bl1);
                }
#pragma unroll
                for (int mi = 0; mi < 4; mi++) {
                    mma_bf16(acc[mi][np * 2],     al[mi], bh0);
                    mma_bf16(acc[mi][np * 2 + 1], al[mi], bh1);
                }
            }
        }
    }

    // epilogue
#pragma unroll
    for (int mi = 0; mi < 4; mi++) {
        int r = row0 + warp_m * 64 + mi * 16 + g;       // rows r, r+8
#pragma unroll
        for (int ni = 0; ni < 4; ni++) {
            int col = col0 + warp_n * 32 + ni * 8 + tig * 2;
            if (OutF) {
                *(float2*)&OutF[(size_t)r * HIDDEN + col] =
                    make_float2(acc[mi][ni][0], acc[mi][ni][1]);
                *(float2*)&OutF[(size_t)(r + 8) * HIDDEN + col] =
                    make_float2(acc[mi][ni][2], acc[mi][ni][3]);
            } else {
                int h = col >> 6, d = col & 63;
                int b0 = r >> 11, s0 = r & 2047;
                int b1 = (r + 8) >> 11, s1 = (r + 8) & 2047;
                size_t i0 = (((size_t)(b0 * HEADS + h)) * SEQ + s0) * HDIM + d;
                size_t i1 = (((size_t)(b1 * HEADS + h)) * SEQ + s1) * HDIM + d;
                uint32_t hi, lo;
                hilo2(acc[mi][ni][0] * oscale, acc[mi][ni][1] * oscale, hi, lo);
                *(uint32_t*)&OutHi[i0] = hi;  *(uint32_t*)&OutLo[i0] = lo;
                hilo2(acc[mi][ni][2] * oscale, acc[mi][ni][3] * oscale, hi, lo);
                *(uint32_t*)&OutHi[i1] = hi;  *(uint32_t*)&OutLo[i1] = lo;
            }
        }
    }
}

__global__ __launch_bounds__(256, 2) void gemm_qkv() {
    const int z = blockIdx.z;
    const size_t zoff = (size_t)z * HIDDEN * HIDDEN;
    bf16* oh = (z == 0) ? g_qhi : (z == 1) ? g_khi : g_vhi;
    bf16* ol = (z == 0) ? g_qlo : (z == 1) ? g_klo : g_vlo;
    float sc = (z == 0) ? QK_SCALE2 : 1.0f;   // fold softmax scale into Q
    gemm_body(s_xhi, s_xlo, s_whi + zoff, s_wlo + zoff, oh, ol, nullptr, sc);
}
__global__ __launch_bounds__(256, 2) void gemm_out(float* __restrict__ out) {
    const size_t zoff = (size_t)3 * HIDDEN * HIDDEN;
    gemm_body(g_ohi, g_olo, s_whi + zoff, s_wlo + zoff, nullptr, nullptr, out, 1.0f);
}

// ---------------------------------------------------------------------------
// Flash attention, split-bf16, Br=128, Bc=128, 8 warps, 2 KV buffers.
// Q pre-scaled by 0.125*log2(e); softmax in exp2 domain.
// Flat grid, globally heavy-first. PV phase chunk-interleaved with exp2/pack
// so MUFU/ALU issue overlaps draining HMMA within each warp.
// ---------------------------------------------------------------------------
#define FQ_B   (128 * 128)              // 16384 bytes per Q matrix
#define FKV_B  (128 * 128)              // 16384 per KV matrix (128 rows x 128B)
#define OQH    0
#define OQL    FQ_B
#define OKV    (2 * FQ_B)
#define FSTAGE_B (4 * FKV_B)            // KH,KL,VH,VL = 65536
#define FSMEM  (2 * FQ_B + 2 * FSTAGE_B)   // 163840

// 128B rows, XOR swizzle on the 16B column within the row
__device__ __forceinline__ uint32_t fsw(uint32_t r, uint32_t cb) {
    return r * 128u + ((((cb >> 4) ^ r) & 7u) << 4);
}

__global__ __launch_bounds__(256) void flash_tc()
{
    extern __shared__ __align__(16) char fsm[];
    const uint32_t sb = smem_u32(fsm);

    const int tid = threadIdx.x;
    const int lane = tid & 31;
    const int wid = tid >> 5;
    const int g = lane >> 2, tig = lane & 3;
    // globally heavy-first: first 148 CTAs are the heaviest diagonal blocks
    const int idx = (int)blockIdx.x;
    const int bh = idx & 31;
    const int bx = (SEQ / 128 - 1) - (idx >> 5);      // 15 .. 0
    const int q0 = bx * 128;
    const size_t bho = (size_t)bh * SEQ * HDIM;
    const int nt = bx + 1;

    // ---- prologue loads ----
    {
        const bf16* qsrc[2] = {g_qhi + bho, g_qlo + bho};
#pragma unroll
        for (int m = 0; m < 2; m++)
#pragma unroll
            for (int i = 0; i < 4; i++) {
                int ci = tid + i * 256;            // 1024 chunks
                int r = ci >> 3, c = ci & 7;
                cp16(sb + (m ? OQL : OQH) + fsw(r, c * 16),
                     qsrc[m] + (size_t)(q0 + r) * HDIM + c * 8);
            }
    }
    auto load_kv = [&](int t, int buf) {
        const int j0 = t * 128;
        const bf16* src[4] = {g_khi + bho, g_klo + bho, g_vhi + bho, g_vlo + bho};
        uint32_t base = sb + OKV + buf * FSTAGE_B;
#pragma unroll
        for (int m = 0; m < 4; m++)
#pragma unroll
            for (int i = 0; i < 4; i++) {
                int ci = tid + i * 256;            // 1024 chunks per matrix
                int r = ci >> 3, c = ci & 7;
                cp16(base + m * FKV_B + fsw(r, c * 16),
                     src[m] + (size_t)(j0 + r) * HDIM + c * 8);
            }
    };
    load_kv(0, 0);
    CP_COMMIT();                        // group: Q + KV0
    if (nt > 1) load_kv(1, 1);
    CP_COMMIT();                        // group: KV1 (possibly empty)

    const uint32_t a_row = (uint32_t)(((lane >> 3) & 1) * 8 + (lane & 7));
    const uint32_t a_cb  = (uint32_t)((lane >> 4) * 16);
    const uint32_t b_row = (uint32_t)((lane >> 4) * 8 + (lane & 7));
    const uint32_t b_cb  = (uint32_t)(((lane >> 3) & 1) * 16);
    const uint32_t q_row = (uint32_t)(wid * 16) + a_row;

    float m0 = -1e30f, m1 = -1e30f, l0 = 0.f, l1 = 0.f;
    float o[8][4];
#pragma unroll
    for (int dt = 0; dt < 8; dt++)
#pragma unroll
        for (int e = 0; e < 4; e++) o[dt][e] = 0.f;

    for (int t = 0; t < nt; t++) {
        CP_WAIT1();
        __syncthreads();
        const uint32_t kvb = sb + OKV + (t & 1) * FSTAGE_B;

        // ---- S = Q K^T (scores already in log2 domain via pre-scaled Q) ----
        float s[16][4];
#pragma unroll
        for (int j = 0; j < 16; j++)
#pragma unroll
            for (int e = 0; e < 4; e++) s[j][e] = 0.f;
#pragma unroll
        for (int ks = 0; ks < 4; ks++) {
            const uint32_t cbq = (uint32_t)(ks * 32) + a_cb;
            uint32_t qh[4], ql[4];
            ldsm4(qh[0], qh[1], qh[2], qh[3], sb + OQH + fsw(q_row, cbq));
            ldsm4(ql[0], ql[1], ql[2], ql[3], sb + OQL + fsw(q_row, cbq));
            const uint32_t cb = (uint32_t)(ks * 32) + b_cb;
#pragma unroll
            for (int npp = 0; npp < 4; npp++) {    // pairs of n16 groups
                uint32_t kh[4][2], kl[4][2];
#pragma unroll
                for (int q = 0; q < 2; q++) {
                    uint32_t n = (uint32_t)((npp * 2 + q) * 16) + b_row;
                    uint32_t h0, h1, h2, h3, l0r, l1r, l2r, l3r;
                    ldsm4(h0, h1, h2, h3, kvb + 0 * FKV_B + fsw(n, cb));
                    ldsm4(l0r, l1r, l2r, l3r, kvb + 1 * FKV_B + fsw(n, cb));
                    kh[q * 2][0] = h0;  kh[q * 2][1] = h1;
                    kh[q * 2 + 1][0] = h2;  kh[q * 2 + 1][1] = h3;
                    kl[q * 2][0] = l0r;  kl[q * 2][1] = l1r;
                    kl[q * 2 + 1][0] = l2r;  kl[q * 2 + 1][1] = l3r;
                }
#pragma unroll
                for (int a = 0; a < 4; a++) mma_bf16(s[npp * 4 + a], qh, kh[a]);
#pragma unroll
                for (int a = 0; a < 4; a++) mma_bf16(s[npp * 4 + a], qh, kl[a]);
#pragma unroll
                for (int a = 0; a < 4; a++) mma_bf16(s[npp * 4 + a], ql, kh[a]);
            }
        }

        // ---- causal mask (diagonal tile only; uniform branch) ----
        if (t == bx) {
            const int j0 = t * 128;
            const int r0 = q0 + wid * 16 + g;
#pragma unroll
            for (int j = 0; j < 16; j++) {
#pragma unroll
                for (int e = 0; e < 4; e++) {
                    int col = j0 + j * 8 + tig * 2 + (e & 1);
                    int row = r0 + ((e >> 1) * 8);
                    if (col > row) s[j][e] = -1e9f;
                }
            }
        }

        // ---- row max (rows g and g+8) ----
        float mx0 = -1e30f, mx1 = -1e30f;
#pragma unroll
        for (int j = 0; j < 16; j++) {
            mx0 = fmaxf(mx0, fmaxf(s[j][0], s[j][1]));
            mx1 = fmaxf(mx1, fmaxf(s[j][2], s[j][3]));
        }
        mx0 = fmaxf(mx0, __shfl_xor_sync(0xffffffffu, mx0, 1));
        mx0 = fmaxf(mx0, __shfl_xor_sync(0xffffffffu, mx0, 2));
        mx1 = fmaxf(mx1, __shfl_xor_sync(0xffffffffu, mx1, 1));
        mx1 = fmaxf(mx1, __shfl_xor_sync(0xffffffffu, mx1, 2));
        float mn0 = fmaxf(m0, mx0), mn1 = fmaxf(m1, mx1);
        float al0 = exp2f(m0 - mn0), al1 = exp2f(m1 - mn1);
        m0 = mn0;  m1 = mn1;
#pragma unroll
        for (int dt = 0; dt < 8; dt++) {
            o[dt][0] *= al0; o[dt][1] *= al0;
            o[dt][2] *= al1; o[dt][3] *= al1;
        }
        float sum0 = 0.f, sum1 = 0.f;

        // ---- chunk-interleaved exp2/pack + PV: MUFU overlaps HMMA drain ----
#pragma unroll
        for (int kp = 0; kp < 8; kp++) {
            float p00 = exp2f(s[2 * kp][0] - mn0);
            float p01 = exp2f(s[2 * kp][1] - mn0);
            float p02 = exp2f(s[2 * kp][2] - mn1);
            float p03 = exp2f(s[2 * kp][3] - mn1);
            float p10 = exp2f(s[2 * kp + 1][0] - mn0);
            float p11 = exp2f(s[2 * kp + 1][1] - mn0);
            float p12 = exp2f(s[2 * kp + 1][2] - mn1);
            float p13 = exp2f(s[2 * kp + 1][3] - mn1);
            sum0 += p00 + p01 + p10 + p11;
            sum1 += p02 + p03 + p12 + p13;
            uint32_t ph[4], pl[4];
            hilo2(p00, p01, ph[0], pl[0]);
            hilo2(p02, p03, ph[1], pl[1]);
            hilo2(p10, p11, ph[2], pl[2]);
            hilo2(p12, p13, ph[3], pl[3]);
            uint32_t kr = (uint32_t)(kp * 16) + a_row;     // kv row within tile
#pragma unroll
            for (int npp = 0; npp < 2; npp++) {
                uint32_t vh[4][2], vl[4][2];
#pragma unroll
                for (int q = 0; q < 2; q++) {
                    uint32_t cb = (uint32_t)((npp * 2 + q) * 32) + a_cb;
                    uint32_t v0, v1, v2, v3, w0, w1, w2, w3;
                    ldsm4t(v0, v1, v2, v3, kvb + 2 * FKV_B + fsw(kr, cb));
                    ldsm4t(w0, w1, w2, w3, kvb + 3 * FKV_B + fsw(kr, cb));
                    vh[q * 2][0] = v0;  vh[q * 2][1] = v1;
                    vh[q * 2 + 1][0] = v2;  vh[q * 2 + 1][1] = v3;
                    vl[q * 2][0] = w0;  vl[q * 2][1] = w1;
                    vl[q * 2 + 1][0] = w2;  vl[q * 2 + 1][1] = w3;
                }
#pragma unroll
                for (int a = 0; a < 4; a++) mma_bf16(o[npp * 4 + a], ph, vh[a]);
#pragma unroll
                for (int a = 0; a < 4; a++) mma_bf16(o[npp * 4 + a], ph, vl[a]);
#pragma unroll
                for (int a = 0; a < 4; a++) mma_bf16(o[npp * 4 + a], pl, vh[a]);
            }
        }

        // ---- lane-sum reduction + l update ----
        sum0 += __shfl_xor_sync(0xffffffffu, sum0, 1);
        sum0 += __shfl_xor_sync(0xffffffffu, sum0, 2);
        sum1 += __shfl_xor_sync(0xffffffffu, sum1, 1);
        sum1 += __shfl_xor_sync(0xffffffffu, sum1, 2);
        l0 = l0 * al0 + sum0;
        l1 = l1 * al1 + sum1;

        __syncthreads();
        if (t + 2 < nt) load_kv(t + 2, t & 1);
        CP_COMMIT();
    }

    // ---- epilogue: O/l -> bf16 hi/lo at [b][s][h*64+d] ----
    const int b = bh >> 4, h = bh & 15;
    const int s0 = q0 + wid * 16 + g;
    const float i0 = 1.f / l0, i1 = 1.f / l1;
#pragma unroll
    for (int dt = 0; dt < 8; dt++) {
        int d = dt * 8 + tig * 2;
        size_t base0 = ((size_t)(b * SEQ) + s0) * HIDDEN + h * HDIM + d;
        size_t base1 = base0 + (size_t)8 * HIDDEN;
        uint32_t hi, lo;
        hilo2(o[dt][0] * i0, o[dt][1] * i0, hi, lo);
        *(uint32_t*)&g_ohi[base0] = hi;  *(uint32_t*)&g_olo[base0] = lo;
        hilo2(o[dt][2] * i1, o[dt][3] * i1, hi, lo);
        *(uint32_t*)&g_ohi[base1] = hi;  *(uint32_t*)&g_olo[base1] = lo;
    }
}

// ---------------------------------------------------------------------------
// Launch
// ---------------------------------------------------------------------------
extern "C" void kernel_launch(void* const* d_in, const int* in_sizes, int n_in,
                              void* d_out, int out_size)
{
    const float* X  = (const float*)d_in[0];
    // d_in[1] = attention_mask (exact causal; applied analytically)
    const float* Wq = (const float*)d_in[2];
    const float* Wk = (const float*)d_in[3];
    const float* Wv = (const float*)d_in[4];
    const float* Wo = (const float*)d_in[5];
    float* out = (float*)d_out;

    cudaFuncSetAttribute(gemm_qkv, cudaFuncAttributeMaxDynamicSharedMemorySize, GSMEM);
    cudaFuncSetAttribute(gemm_out, cudaFuncAttributeMaxDynamicSharedMemorySize, GSMEM);
    cudaFuncSetAttribute(flash_tc, cudaFuncAttributeMaxDynamicSharedMemorySize, FSMEM);

    convert_x<<<NTOK * HIDDEN / 1024, 256>>>(X);
    transpose_w<<<dim3(32, 32, 4), dim3(32, 8)>>>(Wq, Wk, Wv, Wo);

    gemm_qkv<<<dim3(HIDDEN / 128, NTOK / 128, 3), 256, GSMEM>>>();

    flash_tc<<<(SEQ / 128) * BATCH * HEADS, 256, FSMEM>>>();

    gemm_out<<<dim3(HIDDEN / 128, NTOK / 128), 256, GSMEM>>>(out);
}

// round 14
// speedup vs baseline: 1.0653x; 1.0514x over previous
#include <cuda_runtime.h>
#include <cuda_bf16.h>
#include <cstdint>

#define BATCH   2
#define SEQ     2048
#define HIDDEN  1024
#define HEADS   16
#define HDIM    64
#define NTOK    (BATCH * SEQ)          // 4096
#define QK_SCALE2 0.18033688f           // 0.125 * log2(e)

typedef __nv_bfloat16 bf16;

// ---------------------------------------------------------------------------
// Device scratch (no cudaMalloc allowed)
// ---------------------------------------------------------------------------
__device__ bf16 s_xhi[NTOK * HIDDEN];               // X split-bf16
__device__ bf16 s_xlo[NTOK * HIDDEN];
__device__ bf16 s_whi[4 * HIDDEN * HIDDEN];         // W^T split-bf16 (q,k,v,o)
__device__ bf16 s_wlo[4 * HIDDEN * HIDDEN];
__device__ bf16 g_qhi[BATCH * HEADS * SEQ * HDIM];  // [B,H,S,D] (Q pre-scaled)
__device__ bf16 g_qlo[BATCH * HEADS * SEQ * HDIM];
__device__ bf16 g_khi[BATCH * HEADS * SEQ * HDIM];
__device__ bf16 g_klo[BATCH * HEADS * SEQ * HDIM];
__device__ bf16 g_vhi[BATCH * HEADS * SEQ * HDIM];
__device__ bf16 g_vlo[BATCH * HEADS * SEQ * HDIM];
__device__ bf16 g_ohi[NTOK * HIDDEN];               // attention out [B,S,H*D]
__device__ bf16 g_olo[NTOK * HIDDEN];

// ---------------------------------------------------------------------------
// PTX helpers
// ---------------------------------------------------------------------------
__device__ __forceinline__ uint32_t smem_u32(const void* p) {
    uint32_t a;
    asm("{ .reg .u64 t; cvta.to.shared.u64 t, %1; cvt.u32.u64 %0, t; }" : "=r"(a) : "l"(p));
    return a;
}
__device__ __forceinline__ void cp16(uint32_t s, const void* g) {
    asm volatile("cp.async.cg.shared.global [%0], [%1], 16;" :: "r"(s), "l"(g) : "memory");
}
#define CP_COMMIT() asm volatile("cp.async.commit_group;" ::: "memory")
#define CP_WAIT0()  asm volatile("cp.async.wait_group 0;" ::: "memory")
#define CP_WAIT1()  asm volatile("cp.async.wait_group 1;" ::: "memory")

__device__ __forceinline__ void ldsm4(uint32_t& r0, uint32_t& r1, uint32_t& r2, uint32_t& r3, uint32_t a) {
    asm volatile("ldmatrix.sync.aligned.m8n8.x4.shared.b16 {%0,%1,%2,%3}, [%4];"
                 : "=r"(r0), "=r"(r1), "=r"(r2), "=r"(r3) : "r"(a));
}
__device__ __forceinline__ void ldsm4t(uint32_t& r0, uint32_t& r1, uint32_t& r2, uint32_t& r3, uint32_t a) {
    asm volatile("ldmatrix.sync.aligned.m8n8.x4.trans.shared.b16 {%0,%1,%2,%3}, [%4];"
                 : "=r"(r0), "=r"(r1), "=r"(r2), "=r"(r3) : "r"(a));
}
__device__ __forceinline__ void mma_bf16(float d[4], const uint32_t a[4], const uint32_t b[2]) {
    asm volatile(
        "mma.sync.aligned.m16n8k16.row.col.f32.bf16.bf16.f32 "
        "{%0,%1,%2,%3}, {%4,%5,%6,%7}, {%8,%9}, {%0,%1,%2,%3};"
        : "+f"(d[0]), "+f"(d[1]), "+f"(d[2]), "+f"(d[3])
        : "r"(a[0]), "r"(a[1]), "r"(a[2]), "r"(a[3]), "r"(b[0]), "r"(b[1]));
}
// split x,y into packed bf16 hi pair + lo pair (packed cvt)
__device__ __forceinline__ void hilo2(float x, float y, uint32_t& hi, uint32_t& lo) {
    __nv_bfloat162 h2 = __floats2bfloat162_rn(x, y);   // x->low, y->high
    float rx = x - __bfloat162float(h2.x);
    float ry = y - __bfloat162float(h2.y);
    __nv_bfloat162 l2 = __floats2bfloat162_rn(rx, ry);
    hi = *reinterpret_cast<uint32_t*>(&h2);
    lo = *reinterpret_cast<uint32_t*>(&l2);
}

// 128B rows, XOR swizzle on the 16B column within the row (shared by GEMM+flash)
__device__ __forceinline__ uint32_t fsw(uint32_t r, uint32_t cb) {
    return r * 128u + ((((cb >> 4) ^ r) & 7u) << 4) + (cb & 15u);
}

// ---------------------------------------------------------------------------
// Pre-convert kernels
// ---------------------------------------------------------------------------
__global__ __launch_bounds__(256) void convert_x(const float* __restrict__ X) {
    size_t i4 = ((size_t)blockIdx.x * 256 + threadIdx.x) * 4;
    float4 v = *(const float4*)&X[i4];
    uint32_t h0, l0, h1, l1;
    hilo2(v.x, v.y, h0, l0);
    hilo2(v.z, v.w, h1, l1);
    *(uint32_t*)&s_xhi[i4]     = h0;  *(uint32_t*)&s_xhi[i4 + 2] = h1;
    *(uint32_t*)&s_xlo[i4]     = l0;  *(uint32_t*)&s_xlo[i4 + 2] = l1;
}

// W [k][n] -> Wt [n][k] split-bf16, 32x32 tiles
__global__ __launch_bounds__(256) void transpose_w(
    const float* __restrict__ w0, const float* __restrict__ w1,
    const float* __restrict__ w2, const float* __restrict__ w3)
{
    __shared__ float t[32][33];
    const int z = blockIdx.z;
    const float* W = (z == 0) ? w0 : (z == 1) ? w1 : (z == 2) ? w2 : w3;
    const size_t zoff = (size_t)z * HIDDEN * HIDDEN;
    const int n0 = blockIdx.x * 32, k0 = blockIdx.y * 32;
    const int tx = threadIdx.x, ty = threadIdx.y;   // 32 x 8
#pragma unroll
    for (int i = 0; i < 4; i++)
        t[ty + i * 8][tx] = W[(size_t)(k0 + ty + i * 8) * HIDDEN + n0 + tx];
    __syncthreads();
#pragma unroll
    for (int i = 0; i < 4; i++) {
        int nr = ty + i * 8;
        float v = t[tx][nr];
        bf16 h = __float2bfloat16_rn(v);
        bf16 l = __float2bfloat16_rn(v - __bfloat162float(h));
        s_whi[zoff + (size_t)(n0 + nr) * HIDDEN + k0 + tx] = h;
        s_wlo[zoff + (size_t)(n0 + nr) * HIDDEN + k0 + tx] = l;
    }
}

// ---------------------------------------------------------------------------
// Split-bf16 GEMM: C[4096x1024] = A @ Wt^T ; A,Wt row-major bf16 hi/lo.
// Block 128x128xBK32. Smem: dense 128B rows [hi 64B | lo 64B], XOR swizzle.
// 3-stage cp.async (loads issued 2 iters ahead), 8 warps, 2 CTAs/SM.
// ---------------------------------------------------------------------------
#define GBK     32
#define GKITERS (HIDDEN / GBK)          // 32
#define G2T_B   (128 * 128)             // 16384: one tile (hi|lo interleaved)
#define OA2     0
#define OB2     G2T_B
#define G2STAGE (2 * G2T_B)             // 32768
#define G2NST   3
#define GSMEM   (G2NST * G2STAGE)       // 98304 (x2 CTAs = 196K <= 227K)

__device__ __forceinline__ void gemm_load_stage(
    uint32_t sb, const bf16* __restrict__ Ahi, const bf16* __restrict__ Alo,
    const bf16* __restrict__ Bhi, const bf16* __restrict__ Blo,
    int row0, int col0, int kc, int tid)
{
    const int k0 = kc * GBK;
#pragma unroll
    for (int i = 0; i < 8; i++) {
        int ci  = tid + i * 256;        // 2048 chunks total
        int mat = ci >> 10;             // 0 = A, 1 = B
        int idx = ci & 1023;
        int r   = idx >> 3;             // 0..127
        int c   = idx & 7;              // 0..7 (c<4: hi, c>=4: lo)
        uint32_t dst = sb + (mat ? OB2 : OA2) + fsw((uint32_t)r, (uint32_t)(c * 16));
        const bf16* src;
        size_t off = (size_t)((mat ? col0 : row0) + r) * HIDDEN + k0 + (c & 3) * 8;
        if (mat == 0) src = (c < 4) ? Ahi + off : Alo + off;
        else          src = (c < 4) ? Bhi + off : Blo + off;
        cp16(dst, src);
    }
}

__device__ __forceinline__ void gemm_body(
    const bf16* __restrict__ Ahi, const bf16* __restrict__ Alo,
    const bf16* __restrict__ Bhi, const bf16* __restrict__ Blo,
    bf16* __restrict__ OutHi, bf16* __restrict__ OutLo,   // mode qkv (permuted)
    float* __restrict__ OutF,                             // mode fp32 row-major
    float oscale)
{
    extern __shared__ __align__(16) char gsm[];
    const uint32_t sb0 = smem_u32(gsm);

    const int tid = threadIdx.x;        // 256 threads
    const int lane = tid & 31;
    const int wid = tid >> 5;           // 0..7
    const int g = lane >> 2, tig = lane & 3;
    const int warp_m = wid >> 2;        // 0..1 (64 rows)
    const int warp_n = wid & 3;         // 0..3 (32 cols)
    const int row0 = blockIdx.y * 128;
    const int col0 = blockIdx.x * 128;

    float acc[4][4][4];
#pragma unroll
    for (int mi = 0; mi < 4; mi++)
#pragma unroll
        for (int ni = 0; ni < 4; ni++)
#pragma unroll
            for (int e = 0; e < 4; e++) acc[mi][ni][e] = 0.f;

    // prologue: stages 0, 1
    gemm_load_stage(sb0,           Ahi, Alo, Bhi, Blo, row0, col0, 0, tid);
    CP_COMMIT();
    gemm_load_stage(sb0 + G2STAGE, Ahi, Alo, Bhi, Blo, row0, col0, 1, tid);
    CP_COMMIT();

    const uint32_t a_row = (uint32_t)(((lane >> 3) & 1) * 8 + (lane & 7));
    const uint32_t a_cb  = (uint32_t)((lane >> 4) * 16);
    const uint32_t b_row = (uint32_t)((lane >> 4) * 8 + (lane & 7));
    const uint32_t b_cb  = (uint32_t)(((lane >> 3) & 1) * 16);

    int stage = 0;   // buffer index of current compute stage
    for (int kc = 0; kc < GKITERS; kc++) {
        CP_WAIT1();              // stage kc complete (kc+1 may still fly)
        __syncthreads();
        if (kc + 2 < GKITERS) {
            int nb = stage;      // buffer being freed after this compute? no:
            nb = (stage + 2) % G2NST;
            gemm_load_stage(sb0 + nb * G2STAGE, Ahi, Alo, Bhi, Blo,
                            row0, col0, kc + 2, tid);
        }
        CP_COMMIT();

        const uint32_t sb = sb0 + stage * G2STAGE;
#pragma unroll
        for (int ks = 0; ks < 2; ks++) {           // two k16 slices
            const uint32_t cbA = (uint32_t)(ks * 32) + a_cb;
            const uint32_t cbB = (uint32_t)(ks * 32) + b_cb;
            uint32_t ah[4][4], al[4][4];
#pragma unroll
            for (int mi = 0; mi < 4; mi++) {
                uint32_t r = (uint32_t)(warp_m * 64 + mi * 16) + a_row;
                ldsm4(ah[mi][0], ah[mi][1], ah[mi][2], ah[mi][3],
                      sb + OA2 + fsw(r, cbA));
                ldsm4(al[mi][0], al[mi][1], al[mi][2], al[mi][3],
                      sb + OA2 + fsw(r, 64u + cbA));
            }
#pragma unroll
            for (int np = 0; np < 2; np++) {       // n16 pairs (32 cols)
                uint32_t n = (uint32_t)(warp_n * 32 + np * 16) + b_row;
                uint32_t h0, h1, h2, h3, l0, l1, l2, l3;
                ldsm4(h0, h1, h2, h3, sb + OB2 + fsw(n, cbB));
                ldsm4(l0, l1, l2, l3, sb + OB2 + fsw(n, 64u + cbB));
                uint32_t bh0[2] = {h0, h1}, bh1[2] = {h2, h3};
                uint32_t bl0[2] = {l0, l1}, bl1[2] = {l2, l3};
#pragma unroll
                for (int mi = 0; mi < 4; mi++) {
                    mma_bf16(acc[mi][np * 2],     ah[mi], bh0);
                    mma_bf16(acc[mi][np * 2 + 1], ah[mi], bh1);
                }
#pragma unroll
                for (int mi = 0; mi < 4; mi++) {
                    mma_bf16(acc[mi][np * 2],     ah[mi], bl0);
                    mma_bf16(acc[mi][np * 2 + 1], ah[mi], bl1);
                }
#pragma unroll
                for (int mi = 0; mi < 4; mi++) {
                    mma_bf16(acc[mi][np * 2],     al[mi], bh0);
                    mma_bf16(acc[mi][np * 2 + 1], al[mi], bh1);
                }
            }
        }
        stage = (stage + 1) % G2NST;
    }

    // epilogue
#pragma unroll
    for (int mi = 0; mi < 4; mi++) {
        int r = row0 + warp_m * 64 + mi * 16 + g;       // rows r, r+8
#pragma unroll
        for (int ni = 0; ni < 4; ni++) {
            int col = col0 + warp_n * 32 + ni * 8 + tig * 2;
            if (OutF) {
                *(float2*)&OutF[(size_t)r * HIDDEN + col] =
                    make_float2(acc[mi][ni][0], acc[mi][ni][1]);
                *(float2*)&OutF[(size_t)(r + 8) * HIDDEN + col] =
                    make_float2(acc[mi][ni][2], acc[mi][ni][3]);
            } else {
                int h = col >> 6, d = col & 63;
                int b0 = r >> 11, s0 = r & 2047;
                int b1 = (r + 8) >> 11, s1 = (r + 8) & 2047;
                size_t i0 = (((size_t)(b0 * HEADS + h)) * SEQ + s0) * HDIM + d;
                size_t i1 = (((size_t)(b1 * HEADS + h)) * SEQ + s1) * HDIM + d;
                uint32_t hi, lo;
                hilo2(acc[mi][ni][0] * oscale, acc[mi][ni][1] * oscale, hi, lo);
                *(uint32_t*)&OutHi[i0] = hi;  *(uint32_t*)&OutLo[i0] = lo;
                hilo2(acc[mi][ni][2] * oscale, acc[mi][ni][3] * oscale, hi, lo);
                *(uint32_t*)&OutHi[i1] = hi;  *(uint32_t*)&OutLo[i1] = lo;
            }
        }
    }
}

__global__ __launch_bounds__(256, 2) void gemm_qkv() {
    const int z = blockIdx.z;
    const size_t zoff = (size_t)z * HIDDEN * HIDDEN;
    bf16* oh = (z == 0) ? g_qhi : (z == 1) ? g_khi : g_vhi;
    bf16* ol = (z == 0) ? g_qlo : (z == 1) ? g_klo : g_vlo;
    float sc = (z == 0) ? QK_SCALE2 : 1.0f;   // fold softmax scale into Q
    gemm_body(s_xhi, s_xlo, s_whi + zoff, s_wlo + zoff, oh, ol, nullptr, sc);
}
__global__ __launch_bounds__(256, 2) void gemm_out(float* __restrict__ out) {
    const size_t zoff = (size_t)3 * HIDDEN * HIDDEN;
    gemm_body(g_ohi, g_olo, s_whi + zoff, s_wlo + zoff, nullptr, nullptr, out, 1.0f);
}

// ---------------------------------------------------------------------------
// Flash attention, split-bf16, Br=128, Bc=128, 8 warps, 2 KV buffers.
// (unchanged from R12/R13 — proven 161 us)
// ---------------------------------------------------------------------------
#define FQ_B   (128 * 128)              // 16384 bytes per Q matrix
#define FKV_B  (128 * 128)              // 16384 per KV matrix (128 rows x 128B)
#define OQH    0
#define OQL    FQ_B
#define OKV    (2 * FQ_B)
#define FSTAGE_B (4 * FKV_B)            // KH,KL,VH,VL = 65536
#define FSMEM  (2 * FQ_B + 2 * FSTAGE_B)   // 163840

__global__ __launch_bounds__(256) void flash_tc()
{
    extern __shared__ __align__(16) char fsm[];
    const uint32_t sb = smem_u32(fsm);

    const int tid = threadIdx.x;
    const int lane = tid & 31;
    const int wid = tid >> 5;
    const int g = lane >> 2, tig = lane & 3;
    const int idx = (int)blockIdx.x;
    const int bh = idx & 31;
    const int bx = (SEQ / 128 - 1) - (idx >> 5);      // 15 .. 0
    const int q0 = bx * 128;
    const size_t bho = (size_t)bh * SEQ * HDIM;
    const int nt = bx + 1;

    {
        const bf16* qsrc[2] = {g_qhi + bho, g_qlo + bho};
#pragma unroll
        for (int m = 0; m < 2; m++)
#pragma unroll
            for (int i = 0; i < 4; i++) {
                int ci = tid + i * 256;            // 1024 chunks
                int r = ci >> 3, c = ci & 7;
                cp16(sb + (m ? OQL : OQH) + fsw(r, c * 16),
                     qsrc[m] + (size_t)(q0 + r) * HDIM + c * 8);
            }
    }
    auto load_kv = [&](int t, int buf) {
        const int j0 = t * 128;
        const bf16* src[4] = {g_khi + bho, g_klo + bho, g_vhi + bho, g_vlo + bho};
        uint32_t base = sb + OKV + buf * FSTAGE_B;
#pragma unroll
        for (int m = 0; m < 4; m++)
#pragma unroll
            for (int i = 0; i < 4; i++) {
                int ci = tid + i * 256;            // 1024 chunks per matrix
                int r = ci >> 3, c = ci & 7;
                cp16(base + m * FKV_B + fsw(r, c * 16),
                     src[m] + (size_t)(j0 + r) * HDIM + c * 8);
            }
    };
    load_kv(0, 0);
    CP_COMMIT();
    if (nt > 1) load_kv(1, 1);
    CP_COMMIT();

    const uint32_t a_row = (uint32_t)(((lane >> 3) & 1) * 8 + (lane & 7));
    const uint32_t a_cb  = (uint32_t)((lane >> 4) * 16);
    const uint32_t b_row = (uint32_t)((lane >> 4) * 8 + (lane & 7));
    const uint32_t b_cb  = (uint32_t)(((lane >> 3) & 1) * 16);
    const uint32_t q_row = (uint32_t)(wid * 16) + a_row;

    float m0 = -1e30f, m1 = -1e30f, l0 = 0.f, l1 = 0.f;
    float o[8][4];
#pragma unroll
    for (int dt = 0; dt < 8; dt++)
#pragma unroll
        for (int e = 0; e < 4; e++) o[dt][e] = 0.f;

    for (int t = 0; t < nt; t++) {
        CP_WAIT1();
        __syncthreads();
        const uint32_t kvb = sb + OKV + (t & 1) * FSTAGE_B;

        float s[16][4];
#pragma unroll
        for (int j = 0; j < 16; j++)
#pragma unroll
            for (int e = 0; e < 4; e++) s[j][e] = 0.f;
#pragma unroll
        for (int ks = 0; ks < 4; ks++) {
            const uint32_t cbq = (uint32_t)(ks * 32) + a_cb;
            uint32_t qh[4], ql[4];
            ldsm4(qh[0], qh[1], qh[2], qh[3], sb + OQH + fsw(q_row, cbq));
            ldsm4(ql[0], ql[1], ql[2], ql[3], sb + OQL + fsw(q_row, cbq));
            const uint32_t cb = (uint32_t)(ks * 32) + b_cb;
#pragma unroll
            for (int npp = 0; npp < 4; npp++) {
                uint32_t kh[4][2], kl[4][2];
#pragma unroll
                for (int q = 0; q < 2; q++) {
                    uint32_t n = (uint32_t)((npp * 2 + q) * 16) + b_row;
                    uint32_t h0, h1, h2, h3, l0r, l1r, l2r, l3r;
                    ldsm4(h0, h1, h2, h3, kvb + 0 * FKV_B + fsw(n, cb));
                    ldsm4(l0r, l1r, l2r, l3r, kvb + 1 * FKV_B + fsw(n, cb));
                    kh[q * 2][0] = h0;  kh[q * 2][1] = h1;
                    kh[q * 2 + 1][0] = h2;  kh[q * 2 + 1][1] = h3;
                    kl[q * 2][0] = l0r;  kl[q * 2][1] = l1r;
                    kl[q * 2 + 1][0] = l2r;  kl[q * 2 + 1][1] = l3r;
                }
#pragma unroll
                for (int a = 0; a < 4; a++) mma_bf16(s[npp * 4 + a], qh, kh[a]);
#pragma unroll
                for (int a = 0; a < 4; a++) mma_bf16(s[npp * 4 + a], qh, kl[a]);
#pragma unroll
                for (int a = 0; a < 4; a++) mma_bf16(s[npp * 4 + a], ql, kh[a]);
            }
        }

        if (t == bx) {
            const int j0 = t * 128;
            const int r0 = q0 + wid * 16 + g;
#pragma unroll
            for (int j = 0; j < 16; j++) {
#pragma unroll
                for (int e = 0; e < 4; e++) {
                    int col = j0 + j * 8 + tig * 2 + (e & 1);
                    int row = r0 + ((e >> 1) * 8);
                    if (col > row) s[j][e] = -1e9f;
                }
            }
        }

        float mx0 = -1e30f, mx1 = -1e30f;
#pragma unroll
        for (int j = 0; j < 16; j++) {
            mx0 = fmaxf(mx0, fmaxf(s[j][0], s[j][1]));
            mx1 = fmaxf(mx1, fmaxf(s[j][2], s[j][3]));
        }
        mx0 = fmaxf(mx0, __shfl_xor_sync(0xffffffffu, mx0, 1));
        mx0 = fmaxf(mx0, __shfl_xor_sync(0xffffffffu, mx0, 2));
        mx1 = fmaxf(mx1, __shfl_xor_sync(0xffffffffu, mx1, 1));
        mx1 = fmaxf(mx1, __shfl_xor_sync(0xffffffffu, mx1, 2));
        float mn0 = fmaxf(m0, mx0), mn1 = fmaxf(m1, mx1);
        float al0 = exp2f(m0 - mn0), al1 = exp2f(m1 - mn1);
        m0 = mn0;  m1 = mn1;
#pragma unroll
        for (int dt = 0; dt < 8; dt++) {
            o[dt][0] *= al0; o[dt][1] *= al0;
            o[dt][2] *= al1; o[dt][3] *= al1;
        }
        float sum0 = 0.f, sum1 = 0.f;

#pragma unroll
        for (int kp = 0; kp < 8; kp++) {
            float p00 = exp2f(s[2 * kp][0] - mn0);
            float p01 = exp2f(s[2 * kp][1] - mn0);
            float p02 = exp2f(s[2 * kp][2] - mn1);
            float p03 = exp2f(s[2 * kp][3] - mn1);
            float p10 = exp2f(s[2 * kp + 1][0] - mn0);
            float p11 = exp2f(s[2 * kp + 1][1] - mn0);
            float p12 = exp2f(s[2 * kp + 1][2] - mn1);
            float p13 = exp2f(s[2 * kp + 1][3] - mn1);
            sum0 += p00 + p01 + p10 + p11;
            sum1 += p02 + p03 + p12 + p13;
            uint32_t ph[4], pl[4];
            hilo2(p00, p01, ph[0], pl[0]);
            hilo2(p02, p03, ph[1], pl[1]);
            hilo2(p10, p11, ph[2], pl[2]);
            hilo2(p12, p13, ph[3], pl[3]);
            uint32_t kr = (uint32_t)(kp * 16) + a_row;
#pragma unroll
            for (int npp = 0; npp < 2; npp++) {
                uint32_t vh[4][2], vl[4][2];
#pragma unroll
                for (int q = 0; q < 2; q++) {
                    uint32_t cb = (uint32_t)((npp * 2 + q) * 32) + a_cb;
                    uint32_t v0, v1, v2, v3, w0, w1, w2, w3;
                    ldsm4t(v0, v1, v2, v3, kvb + 2 * FKV_B + fsw(kr, cb));
                    ldsm4t(w0, w1, w2, w3, kvb + 3 * FKV_B + fsw(kr, cb));
                    vh[q * 2][0] = v0;  vh[q * 2][1] = v1;
                    vh[q * 2 + 1][0] = v2;  vh[q * 2 + 1][1] = v3;
                    vl[q * 2][0] = w0;  vl[q * 2][1] = w1;
                    vl[q * 2 + 1][0] = w2;  vl[q * 2 + 1][1] = w3;
                }
#pragma unroll
                for (int a = 0; a < 4; a++) mma_bf16(o[npp * 4 + a], ph, vh[a]);
#pragma unroll
                for (int a = 0; a < 4; a++) mma_bf16(o[npp * 4 + a], ph, vl[a]);
#pragma unroll
                for (int a = 0; a < 4; a++) mma_bf16(o[npp * 4 + a], pl, vh[a]);
            }
        }

        sum0 += __shfl_xor_sync(0xffffffffu, sum0, 1);
        sum0 += __shfl_xor_sync(0xffffffffu, sum0, 2);
        sum1 += __shfl_xor_sync(0xffffffffu, sum1, 1);
        sum1 += __shfl_xor_sync(0xffffffffu, sum1, 2);
        l0 = l0 * al0 + sum0;
        l1 = l1 * al1 + sum1;

        __syncthreads();
        if (t + 2 < nt) load_kv(t + 2, t & 1);
        CP_COMMIT();
    }

    const int b = bh >> 4, h = bh & 15;
    const int s0 = q0 + wid * 16 + g;
    const float i0 = 1.f / l0, i1 = 1.f / l1;
#pragma unroll
    for (int dt = 0; dt < 8; dt++) {
        int d = dt * 8 + tig * 2;
        size_t base0 = ((size_t)(b * SEQ) + s0) * HIDDEN + h * HDIM + d;
        size_t base1 = base0 + (size_t)8 * HIDDEN;
        uint32_t hi, lo;
        hilo2(o[dt][0] * i0, o[dt][1] * i0, hi, lo);
        *(uint32_t*)&g_ohi[base0] = hi;  *(uint32_t*)&g_olo[base0] = lo;
        hilo2(o[dt][2] * i1, o[dt][3] * i1, hi, lo);
        *(uint32_t*)&g_ohi[base1] = hi;  *(uint32_t*)&g_olo[base1] = lo;
    }
}

// ---------------------------------------------------------------------------
// Launch
// ---------------------------------------------------------------------------
extern "C" void kernel_launch(void* const* d_in, const int* in_sizes, int n_in,
                              void* d_out, int out_size)
{
    const float* X  = (const float*)d_in[0];
    // d_in[1] = attention_mask (exact causal; applied analytically)
    const float* Wq = (const float*)d_in[2];
    const float* Wk = (const float*)d_in[3];
    const float* Wv = (const float*)d_in[4];
    const float* Wo = (const float*)d_in[5];
    float* out = (float*)d_out;

    cudaFuncSetAttribute(gemm_qkv, cudaFuncAttributeMaxDynamicSharedMemorySize, GSMEM);
    cudaFuncSetAttribute(gemm_out, cudaFuncAttributeMaxDynamicSharedMemorySize, GSMEM);
    cudaFuncSetAttribute(flash_tc, cudaFuncAttributeMaxDynamicSharedMemorySize, FSMEM);

    convert_x<<<NTOK * HIDDEN / 1024, 256>>>(X);
    transpose_w<<<dim3(32, 32, 4), dim3(32, 8)>>>(Wq, Wk, Wv, Wo);

    gemm_qkv<<<dim3(HIDDEN / 128, NTOK / 128, 3), 256, GSMEM>>>();

    flash_tc<<<(SEQ / 128) * BATCH * HEADS, 256, FSMEM>>>();

    gemm_out<<<dim3(HIDDEN / 128, NTOK / 128), 256, GSMEM>>>(out);
}

// round 15
// speedup vs baseline: 1.0700x; 1.0044x over previous
#include <cuda_runtime.h>
#include <cuda_bf16.h>
#include <cstdint>

#define BATCH   2
#define SEQ     2048
#define HIDDEN  1024
#define HEADS   16
#define HDIM    64
#define NTOK    (BATCH * SEQ)          // 4096
#define QK_SCALE2 0.18033688f           // 0.125 * log2(e)

typedef __nv_bfloat16 bf16;

// ---------------------------------------------------------------------------
// Device scratch (no cudaMalloc allowed)
// ---------------------------------------------------------------------------
__device__ bf16 s_xhi[NTOK * HIDDEN];               // X split-bf16
__device__ bf16 s_xlo[NTOK * HIDDEN];
__device__ bf16 s_whi[4 * HIDDEN * HIDDEN];         // W^T split-bf16 (q,k,v,o)
__device__ bf16 s_wlo[4 * HIDDEN * HIDDEN];
__device__ bf16 g_qhi[BATCH * HEADS * SEQ * HDIM];  // [B,H,S,D] (Q pre-scaled)
__device__ bf16 g_qlo[BATCH * HEADS * SEQ * HDIM];
__device__ bf16 g_khi[BATCH * HEADS * SEQ * HDIM];
__device__ bf16 g_klo[BATCH * HEADS * SEQ * HDIM];
__device__ bf16 g_vhi[BATCH * HEADS * SEQ * HDIM];
__device__ bf16 g_vlo[BATCH * HEADS * SEQ * HDIM];
__device__ bf16 g_ohi[NTOK * HIDDEN];               // attention out [B,S,H*D]
__device__ bf16 g_olo[NTOK * HIDDEN];

// ---------------------------------------------------------------------------
// PTX helpers
// ---------------------------------------------------------------------------
__device__ __forceinline__ uint32_t smem_u32(const void* p) {
    uint32_t a;
    asm("{ .reg .u64 t; cvta.to.shared.u64 t, %1; cvt.u32.u64 %0, t; }" : "=r"(a) : "l"(p));
    return a;
}
__device__ __forceinline__ void cp16(uint32_t s, const void* g) {
    asm volatile("cp.async.cg.shared.global [%0], [%1], 16;" :: "r"(s), "l"(g) : "memory");
}
#define CP_COMMIT() asm volatile("cp.async.commit_group;" ::: "memory")
#define CP_WAIT0()  asm volatile("cp.async.wait_group 0;" ::: "memory")
#define CP_WAIT1()  asm volatile("cp.async.wait_group 1;" ::: "memory")

__device__ __forceinline__ void ldsm4(uint32_t& r0, uint32_t& r1, uint32_t& r2, uint32_t& r3, uint32_t a) {
    asm volatile("ldmatrix.sync.aligned.m8n8.x4.shared.b16 {%0,%1,%2,%3}, [%4];"
                 : "=r"(r0), "=r"(r1), "=r"(r2), "=r"(r3) : "r"(a));
}
__device__ __forceinline__ void ldsm4t(uint32_t& r0, uint32_t& r1, uint32_t& r2, uint32_t& r3, uint32_t a) {
    asm volatile("ldmatrix.sync.aligned.m8n8.x4.trans.shared.b16 {%0,%1,%2,%3}, [%4];"
                 : "=r"(r0), "=r"(r1), "=r"(r2), "=r"(r3) : "r"(a));
}
__device__ __forceinline__ void mma_bf16(float d[4], const uint32_t a[4], const uint32_t b[2]) {
    asm volatile(
        "mma.sync.aligned.m16n8k16.row.col.f32.bf16.bf16.f32 "
        "{%0,%1,%2,%3}, {%4,%5,%6,%7}, {%8,%9}, {%0,%1,%2,%3};"
        : "+f"(d[0]), "+f"(d[1]), "+f"(d[2]), "+f"(d[3])
        : "r"(a[0]), "r"(a[1]), "r"(a[2]), "r"(a[3]), "r"(b[0]), "r"(b[1]));
}
// split x,y into packed bf16 hi pair + lo pair (packed cvt)
__device__ __forceinline__ void hilo2(float x, float y, uint32_t& hi, uint32_t& lo) {
    __nv_bfloat162 h2 = __floats2bfloat162_rn(x, y);   // x->low, y->high
    float rx = x - __bfloat162float(h2.x);
    float ry = y - __bfloat162float(h2.y);
    __nv_bfloat162 l2 = __floats2bfloat162_rn(rx, ry);
    hi = *reinterpret_cast<uint32_t*>(&h2);
    lo = *reinterpret_cast<uint32_t*>(&l2);
}

// 128B rows, XOR swizzle on the 16B column within the row (shared by GEMM+flash)
__device__ __forceinline__ uint32_t fsw(uint32_t r, uint32_t cb) {
    return r * 128u + ((((cb >> 4) ^ r) & 7u) << 4) + (cb & 15u);
}

// ---------------------------------------------------------------------------
// Pre-convert kernels
// ---------------------------------------------------------------------------
__global__ __launch_bounds__(256) void convert_x(const float* __restrict__ X) {
    size_t i4 = ((size_t)blockIdx.x * 256 + threadIdx.x) * 4;
    float4 v = *(const float4*)&X[i4];
    uint32_t h0, l0, h1, l1;
    hilo2(v.x, v.y, h0, l0);
    hilo2(v.z, v.w, h1, l1);
    *(uint32_t*)&s_xhi[i4]     = h0;  *(uint32_t*)&s_xhi[i4 + 2] = h1;
    *(uint32_t*)&s_xlo[i4]     = l0;  *(uint32_t*)&s_xlo[i4 + 2] = l1;
}

// W [k][n] -> Wt [n][k] split-bf16, 32x32 tiles
__global__ __launch_bounds__(256) void transpose_w(
    const float* __restrict__ w0, const float* __restrict__ w1,
    const float* __restrict__ w2, const float* __restrict__ w3)
{
    __shared__ float t[32][33];
    const int z = blockIdx.z;
    const float* W = (z == 0) ? w0 : (z == 1) ? w1 : (z == 2) ? w2 : w3;
    const size_t zoff = (size_t)z * HIDDEN * HIDDEN;
    const int n0 = blockIdx.x * 32, k0 = blockIdx.y * 32;
    const int tx = threadIdx.x, ty = threadIdx.y;   // 32 x 8
#pragma unroll
    for (int i = 0; i < 4; i++)
        t[ty + i * 8][tx] = W[(size_t)(k0 + ty + i * 8) * HIDDEN + n0 + tx];
    __syncthreads();
#pragma unroll
    for (int i = 0; i < 4; i++) {
        int nr = ty + i * 8;
        float v = t[tx][nr];
        bf16 h = __float2bfloat16_rn(v);
        bf16 l = __float2bfloat16_rn(v - __bfloat162float(h));
        s_whi[zoff + (size_t)(n0 + nr) * HIDDEN + k0 + tx] = h;
        s_wlo[zoff + (size_t)(n0 + nr) * HIDDEN + k0 + tx] = l;
    }
}

// ---------------------------------------------------------------------------
// Split-bf16 GEMM: C[4096x1024] = A @ Wt^T ; A,Wt row-major bf16 hi/lo.
// Block 256x128xBK32, 8 warps (warp tile 64x64: 4m x 2n), 1 CTA/SM.
// Smem: dense 128B rows [hi 64B | lo 64B], XOR swizzle, 3-stage cp.async.
// B-fragments held/reused over 4 m-tiles -> 85 B smem per MMA.
// ---------------------------------------------------------------------------
#define GBK     32
#define GKITERS (HIDDEN / GBK)          // 32
#define GA_B    (256 * 128)             // 32768: A tile (hi|lo interleaved)
#define GB_B    (128 * 128)             // 16384: B tile
#define OA2     0
#define OB2     GA_B
#define G2STAGE (GA_B + GB_B)           // 49152
#define G2NST   3
#define GSMEM   (G2NST * G2STAGE)       // 147456

__device__ __forceinline__ void gemm_load_stage(
    uint32_t sb, const bf16* __restrict__ Ahi, const bf16* __restrict__ Alo,
    const bf16* __restrict__ Bhi, const bf16* __restrict__ Blo,
    int row0, int col0, int kc, int tid)
{
    const int k0 = kc * GBK;
#pragma unroll
    for (int i = 0; i < 12; i++) {
        int ci = tid + i * 256;         // 3072 chunks: 2048 A + 1024 B
        int isB = (ci >= 2048);
        int idx = isB ? (ci - 2048) : ci;
        int r   = idx >> 3;             // A: 0..255, B: 0..127
        int c   = idx & 7;              // c<4: hi, c>=4: lo
        uint32_t dst = sb + (isB ? OB2 : OA2) + fsw((uint32_t)r, (uint32_t)(c * 16));
        size_t off = (size_t)((isB ? col0 : row0) + r) * HIDDEN + k0 + (c & 3) * 8;
        const bf16* src;
        if (!isB) src = (c < 4) ? Ahi + off : Alo + off;
        else      src = (c < 4) ? Bhi + off : Blo + off;
        cp16(dst, src);
    }
}

__device__ __forceinline__ void gemm_body(
    const bf16* __restrict__ Ahi, const bf16* __restrict__ Alo,
    const bf16* __restrict__ Bhi, const bf16* __restrict__ Blo,
    bf16* __restrict__ OutHi, bf16* __restrict__ OutLo,   // mode qkv (permuted)
    float* __restrict__ OutF,                             // mode fp32 row-major
    float oscale)
{
    extern __shared__ __align__(16) char gsm[];
    const uint32_t sb0 = smem_u32(gsm);

    const int tid = threadIdx.x;        // 256 threads
    const int lane = tid & 31;
    const int wid = tid >> 5;           // 0..7
    const int g = lane >> 2, tig = lane & 3;
    const int warp_m = wid >> 1;        // 0..3 (64 rows each)
    const int warp_n = wid & 1;         // 0..1 (64 cols each)
    const int row0 = blockIdx.y * 256;
    const int col0 = blockIdx.x * 128;

    float acc[4][8][4];
#pragma unroll
    for (int mi = 0; mi < 4; mi++)
#pragma unroll
        for (int nj = 0; nj < 8; nj++)
#pragma unroll
            for (int e = 0; e < 4; e++) acc[mi][nj][e] = 0.f;

    gemm_load_stage(sb0,           Ahi, Alo, Bhi, Blo, row0, col0, 0, tid);
    CP_COMMIT();
    gemm_load_stage(sb0 + G2STAGE, Ahi, Alo, Bhi, Blo, row0, col0, 1, tid);
    CP_COMMIT();

    const uint32_t a_row = (uint32_t)(((lane >> 3) & 1) * 8 + (lane & 7));
    const uint32_t a_cb  = (uint32_t)((lane >> 4) * 16);
    const uint32_t b_row = (uint32_t)((lane >> 4) * 8 + (lane & 7));
    const uint32_t b_cb  = (uint32_t)(((lane >> 3) & 1) * 16);

    int stage = 0;
    for (int kc = 0; kc < GKITERS; kc++) {
        CP_WAIT1();
        __syncthreads();
        if (kc + 2 < GKITERS) {
            int nb = (stage + 2) % G2NST;
            gemm_load_stage(sb0 + nb * G2STAGE, Ahi, Alo, Bhi, Blo,
                            row0, col0, kc + 2, tid);
        }
        CP_COMMIT();

        const uint32_t sb = sb0 + stage * G2STAGE;
#pragma unroll
        for (int ks = 0; ks < 2; ks++) {           // two k16 slices
            const uint32_t cbA = (uint32_t)(ks * 32) + a_cb;
            const uint32_t cbB = (uint32_t)(ks * 32) + b_cb;

            // B fragments: 4 n16 groups, hi+lo, held for all m-tiles (32 regs)
            uint32_t bh[8][2], bl[8][2];
#pragma unroll
            for (int ng = 0; ng < 4; ng++) {
                uint32_t n = (uint32_t)(warp_n * 64 + ng * 16) + b_row;
                uint32_t h0, h1, h2, h3, l0, l1, l2, l3;
                ldsm4(h0, h1, h2, h3, sb + OB2 + fsw(n, cbB));
                ldsm4(l0, l1, l2, l3, sb + OB2 + fsw(n, 64u + cbB));
                bh[ng * 2][0] = h0;     bh[ng * 2][1] = h1;
                bh[ng * 2 + 1][0] = h2; bh[ng * 2 + 1][1] = h3;
                bl[ng * 2][0] = l0;     bl[ng * 2][1] = l1;
                bl[ng * 2 + 1][0] = l2; bl[ng * 2 + 1][1] = l3;
            }

            // A streamed per m-tile; each A pair feeds 24 MMAs
#pragma unroll
            for (int mi = 0; mi < 4; mi++) {
                uint32_t r = (uint32_t)(warp_m * 64 + mi * 16) + a_row;
                uint32_t ah[4], al[4];
                ldsm4(ah[0], ah[1], ah[2], ah[3], sb + OA2 + fsw(r, cbA));
                ldsm4(al[0], al[1], al[2], al[3], sb + OA2 + fsw(r, 64u + cbA));
#pragma unroll
                for (int nj = 0; nj < 8; nj++) mma_bf16(acc[mi][nj], ah, bh[nj]);
#pragma unroll
                for (int nj = 0; nj < 8; nj++) mma_bf16(acc[mi][nj], ah, bl[nj]);
#pragma unroll
                for (int nj = 0; nj < 8; nj++) mma_bf16(acc[mi][nj], al, bh[nj]);
            }
        }
        stage = (stage + 1) % G2NST;
    }

    // epilogue
#pragma unroll
    for (int mi = 0; mi < 4; mi++) {
        int r = row0 + warp_m * 64 + mi * 16 + g;       // rows r, r+8
#pragma unroll
        for (int nj = 0; nj < 8; nj++) {
            int col = col0 + warp_n * 64 + nj * 8 + tig * 2;
            if (OutF) {
                *(float2*)&OutF[(size_t)r * HIDDEN + col] =
                    make_float2(acc[mi][nj][0], acc[mi][nj][1]);
                *(float2*)&OutF[(size_t)(r + 8) * HIDDEN + col] =
                    make_float2(acc[mi][nj][2], acc[mi][nj][3]);
            } else {
                int h = col >> 6, d = col & 63;
                int b0 = r >> 11, s0 = r & 2047;
                int b1 = (r + 8) >> 11, s1 = (r + 8) & 2047;
                size_t i0 = (((size_t)(b0 * HEADS + h)) * SEQ + s0) * HDIM + d;
                size_t i1 = (((size_t)(b1 * HEADS + h)) * SEQ + s1) * HDIM + d;
                uint32_t hi, lo;
                hilo2(acc[mi][nj][0] * oscale, acc[mi][nj][1] * oscale, hi, lo);
                *(uint32_t*)&OutHi[i0] = hi;  *(uint32_t*)&OutLo[i0] = lo;
                hilo2(acc[mi][nj][2] * oscale, acc[mi][nj][3] * oscale, hi, lo);
                *(uint32_t*)&OutHi[i1] = hi;  *(uint32_t*)&OutLo[i1] = lo;
            }
        }
    }
}

__global__ __launch_bounds__(256, 1) void gemm_qkv() {
    const int z = blockIdx.z;
    const size_t zoff = (size_t)z * HIDDEN * HIDDEN;
    bf16* oh = (z == 0) ? g_qhi : (z == 1) ? g_khi : g_vhi;
    bf16* ol = (z == 0) ? g_qlo : (z == 1) ? g_klo : g_vlo;
    float sc = (z == 0) ? QK_SCALE2 : 1.0f;   // fold softmax scale into Q
    gemm_body(s_xhi, s_xlo, s_whi + zoff, s_wlo + zoff, oh, ol, nullptr, sc);
}
__global__ __launch_bounds__(256, 1) void gemm_out(float* __restrict__ out) {
    const size_t zoff = (size_t)3 * HIDDEN * HIDDEN;
    gemm_body(g_ohi, g_olo, s_whi + zoff, s_wlo + zoff, nullptr, nullptr, out, 1.0f);
}

// ---------------------------------------------------------------------------
// Flash attention, split-bf16, Br=128, Bc=128, 8 warps, 2 KV buffers.
// (unchanged — proven 160 us)
// ---------------------------------------------------------------------------
#define FQ_B   (128 * 128)              // 16384 bytes per Q matrix
#define FKV_B  (128 * 128)              // 16384 per KV matrix (128 rows x 128B)
#define OQH    0
#define OQL    FQ_B
#define OKV    (2 * FQ_B)
#define FSTAGE_B (4 * FKV_B)            // KH,KL,VH,VL = 65536
#define FSMEM  (2 * FQ_B + 2 * FSTAGE_B)   // 163840

__global__ __launch_bounds__(256) void flash_tc()
{
    extern __shared__ __align__(16) char fsm[];
    const uint32_t sb = smem_u32(fsm);

    const int tid = threadIdx.x;
    const int lane = tid & 31;
    const int wid = tid >> 5;
    const int g = lane >> 2, tig = lane & 3;
    const int idx = (int)blockIdx.x;
    const int bh = idx & 31;
    const int bx = (SEQ / 128 - 1) - (idx >> 5);      // 15 .. 0
    const int q0 = bx * 128;
    const size_t bho = (size_t)bh * SEQ * HDIM;
    const int nt = bx + 1;

    {
        const bf16* qsrc[2] = {g_qhi + bho, g_qlo + bho};
#pragma unroll
        for (int m = 0; m < 2; m++)
#pragma unroll
            for (int i = 0; i < 4; i++) {
                int ci = tid + i * 256;            // 1024 chunks
                int r = ci >> 3, c = ci & 7;
                cp16(sb + (m ? OQL : OQH) + fsw(r, c * 16),
                     qsrc[m] + (size_t)(q0 + r) * HDIM + c * 8);
            }
    }
    auto load_kv = [&](int t, int buf) {
        const int j0 = t * 128;
        const bf16* src[4] = {g_khi + bho, g_klo + bho, g_vhi + bho, g_vlo + bho};
        uint32_t base = sb + OKV + buf * FSTAGE_B;
#pragma unroll
        for (int m = 0; m < 4; m++)
#pragma unroll
            for (int i = 0; i < 4; i++) {
                int ci = tid + i * 256;            // 1024 chunks per matrix
                int r = ci >> 3, c = ci & 7;
                cp16(base + m * FKV_B + fsw(r, c * 16),
                     src[m] + (size_t)(j0 + r) * HDIM + c * 8);
            }
    };
    load_kv(0, 0);
    CP_COMMIT();
    if (nt > 1) load_kv(1, 1);
    CP_COMMIT();

    const uint32_t a_row = (uint32_t)(((lane >> 3) & 1) * 8 + (lane & 7));
    const uint32_t a_cb  = (uint32_t)((lane >> 4) * 16);
    const uint32_t b_row = (uint32_t)((lane >> 4) * 8 + (lane & 7));
    const uint32_t b_cb  = (uint32_t)(((lane >> 3) & 1) * 16);
    const uint32_t q_row = (uint32_t)(wid * 16) + a_row;

    float m0 = -1e30f, m1 = -1e30f, l0 = 0.f, l1 = 0.f;
    float o[8][4];
#pragma unroll
    for (int dt = 0; dt < 8; dt++)
#pragma unroll
        for (int e = 0; e < 4; e++) o[dt][e] = 0.f;

    for (int t = 0; t < nt; t++) {
        CP_WAIT1();
        __syncthreads();
        const uint32_t kvb = sb + OKV + (t & 1) * FSTAGE_B;

        float s[16][4];
#pragma unroll
        for (int j = 0; j < 16; j++)
#pragma unroll
            for (int e = 0; e < 4; e++) s[j][e] = 0.f;
#pragma unroll
        for (int ks = 0; ks < 4; ks++) {
            const uint32_t cbq = (uint32_t)(ks * 32) + a_cb;
            uint32_t qh[4], ql[4];
            ldsm4(qh[0], qh[1], qh[2], qh[3], sb + OQH + fsw(q_row, cbq));
            ldsm4(ql[0], ql[1], ql[2], ql[3], sb + OQL + fsw(q_row, cbq));
            const uint32_t cb = (uint32_t)(ks * 32) + b_cb;
#pragma unroll
            for (int npp = 0; npp < 4; npp++) {
                uint32_t kh[4][2], kl[4][2];
#pragma unroll
                for (int q = 0; q < 2; q++) {
                    uint32_t n = (uint32_t)((npp * 2 + q) * 16) + b_row;
                    uint32_t h0, h1, h2, h3, l0r, l1r, l2r, l3r;
                    ldsm4(h0, h1, h2, h3, kvb + 0 * FKV_B + fsw(n, cb));
                    ldsm4(l0r, l1r, l2r, l3r, kvb + 1 * FKV_B + fsw(n, cb));
                    kh[q * 2][0] = h0;  kh[q * 2][1] = h1;
                    kh[q * 2 + 1][0] = h2;  kh[q * 2 + 1][1] = h3;
                    kl[q * 2][0] = l0r;  kl[q * 2][1] = l1r;
                    kl[q * 2 + 1][0] = l2r;  kl[q * 2 + 1][1] = l3r;
                }
#pragma unroll
                for (int a = 0; a < 4; a++) mma_bf16(s[npp * 4 + a], qh, kh[a]);
#pragma unroll
                for (int a = 0; a < 4; a++) mma_bf16(s[npp * 4 + a], qh, kl[a]);
#pragma unroll
                for (int a = 0; a < 4; a++) mma_bf16(s[npp * 4 + a], ql, kh[a]);
            }
        }

        if (t == bx) {
            const int j0 = t * 128;
            const int r0 = q0 + wid * 16 + g;
#pragma unroll
            for (int j = 0; j < 16; j++) {
#pragma unroll
                for (int e = 0; e < 4; e++) {
                    int col = j0 + j * 8 + tig * 2 + (e & 1);
                    int row = r0 + ((e >> 1) * 8);
                    if (col > row) s[j][e] = -1e9f;
                }
            }
        }

        float mx0 = -1e30f, mx1 = -1e30f;
#pragma unroll
        for (int j = 0; j < 16; j++) {
            mx0 = fmaxf(mx0, fmaxf(s[j][0], s[j][1]));
            mx1 = fmaxf(mx1, fmaxf(s[j][2], s[j][3]));
        }
        mx0 = fmaxf(mx0, __shfl_xor_sync(0xffffffffu, mx0, 1));
        mx0 = fmaxf(mx0, __shfl_xor_sync(0xffffffffu, mx0, 2));
        mx1 = fmaxf(mx1, __shfl_xor_sync(0xffffffffu, mx1, 1));
        mx1 = fmaxf(mx1, __shfl_xor_sync(0xffffffffu, mx1, 2));
        float mn0 = fmaxf(m0, mx0), mn1 = fmaxf(m1, mx1);
        float al0 = exp2f(m0 - mn0), al1 = exp2f(m1 - mn1);
        m0 = mn0;  m1 = mn1;
#pragma unroll
        for (int dt = 0; dt < 8; dt++) {
            o[dt][0] *= al0; o[dt][1] *= al0;
            o[dt][2] *= al1; o[dt][3] *= al1;
        }
        float sum0 = 0.f, sum1 = 0.f;

#pragma unroll
        for (int kp = 0; kp < 8; kp++) {
            float p00 = exp2f(s[2 * kp][0] - mn0);
            float p01 = exp2f(s[2 * kp][1] - mn0);
            float p02 = exp2f(s[2 * kp][2] - mn1);
            float p03 = exp2f(s[2 * kp][3] - mn1);
            float p10 = exp2f(s[2 * kp + 1][0] - mn0);
            float p11 = exp2f(s[2 * kp + 1][1] - mn0);
            float p12 = exp2f(s[2 * kp + 1][2] - mn1);
            float p13 = exp2f(s[2 * kp + 1][3] - mn1);
            sum0 += p00 + p01 + p10 + p11;
            sum1 += p02 + p03 + p12 + p13;
            uint32_t ph[4], pl[4];
            hilo2(p00, p01, ph[0], pl[0]);
            hilo2(p02, p03, ph[1], pl[1]);
            hilo2(p10, p11, ph[2], pl[2]);
            hilo2(p12, p13, ph[3], pl[3]);
            uint32_t kr = (uint32_t)(kp * 16) + a_row;
#pragma unroll
            for (int npp = 0; npp < 2; npp++) {
                uint32_t vh[4][2], vl[4][2];
#pragma unroll
                for (int q = 0; q < 2; q++) {
                    uint32_t cb = (uint32_t)((npp * 2 + q) * 32) + a_cb;
                    uint32_t v0, v1, v2, v3, w0, w1, w2, w3;
                    ldsm4t(v0, v1, v2, v3, kvb + 2 * FKV_B + fsw(kr, cb));
                    ldsm4t(w0, w1, w2, w3, kvb + 3 * FKV_B + fsw(kr, cb));
                    vh[q * 2][0] = v0;  vh[q * 2][1] = v1;
                    vh[q * 2 + 1][0] = v2;  vh[q * 2 + 1][1] = v3;
                    vl[q * 2][0] = w0;  vl[q * 2][1] = w1;
                    vl[q * 2 + 1][0] = w2;  vl[q * 2 + 1][1] = w3;
                }
#pragma unroll
                for (int a = 0; a < 4; a++) mma_bf16(o[npp * 4 + a], ph, vh[a]);
#pragma unroll
                for (int a = 0; a < 4; a++) mma_bf16(o[npp * 4 + a], ph, vl[a]);
#pragma unroll
                for (int a = 0; a < 4; a++) mma_bf16(o[npp * 4 + a], pl, vh[a]);
            }
        }

        sum0 += __shfl_xor_sync(0xffffffffu, sum0, 1);
        sum0 += __shfl_xor_sync(0xffffffffu, sum0, 2);
        sum1 += __shfl_xor_sync(0xffffffffu, sum1, 1);
        sum1 += __shfl_xor_sync(0xffffffffu, sum1, 2);
        l0 = l0 * al0 + sum0;
        l1 = l1 * al1 + sum1;

        __syncthreads();
        if (t + 2 < nt) load_kv(t + 2, t & 1);
        CP_COMMIT();
    }

    const int b = bh >> 4, h = bh & 15;
    const int s0 = q0 + wid * 16 + g;
    const float i0 = 1.f / l0, i1 = 1.f / l1;
#pragma unroll
    for (int dt = 0; dt < 8; dt++) {
        int d = dt * 8 + tig * 2;
        size_t base0 = ((size_t)(b * SEQ) + s0) * HIDDEN + h * HDIM + d;
        size_t base1 = base0 + (size_t)8 * HIDDEN;
        uint32_t hi, lo;
        hilo2(o[dt][0] * i0, o[dt][1] * i0, hi, lo);
        *(uint32_t*)&g_ohi[base0] = hi;  *(uint32_t*)&g_olo[base0] = lo;
        hilo2(o[dt][2] * i1, o[dt][3] * i1, hi, lo);
        *(uint32_t*)&g_ohi[base1] = hi;  *(uint32_t*)&g_olo[base1] = lo;
    }
}

// ---------------------------------------------------------------------------
// Launch
// ---------------------------------------------------------------------------
extern "C" void kernel_launch(void* const* d_in, const int* in_sizes, int n_in,
                              void* d_out, int out_size)
{
    const float* X  = (const float*)d_in[0];
    // d_in[1] = attention_mask (exact causal; applied analytically)
    const float* Wq = (const float*)d_in[2];
    const float* Wk = (const float*)d_in[3];
    const float* Wv = (const float*)d_in[4];
    const float* Wo = (const float*)d_in[5];
    float* out = (float*)d_out;

    cudaFuncSetAttribute(gemm_qkv, cudaFuncAttributeMaxDynamicSharedMemorySize, GSMEM);
    cudaFuncSetAttribute(gemm_out, cudaFuncAttributeMaxDynamicSharedMemorySize, GSMEM);
    cudaFuncSetAttribute(flash_tc, cudaFuncAttributeMaxDynamicSharedMemorySize, FSMEM);

    convert_x<<<NTOK * HIDDEN / 1024, 256>>>(X);
    transpose_w<<<dim3(32, 32, 4), dim3(32, 8)>>>(Wq, Wk, Wv, Wo);

    gemm_qkv<<<dim3(HIDDEN / 128, NTOK / 256, 3), 256, GSMEM>>>();

    flash_tc<<<(SEQ / 128) * BATCH * HEADS, 256, FSMEM>>>();

    gemm_out<<<dim3(HIDDEN / 128, NTOK / 256), 256, GSMEM>>>(out);
}

// round 16
// speedup vs baseline: 1.5388x; 1.4381x over previous
#include <cuda_runtime.h>
#include <cuda_bf16.h>
#include <cuda_fp16.h>
#include <cstdint>

#define BATCH   2
#define SEQ     2048
#define HIDDEN  1024
#define HEADS   16
#define HDIM    64
#define NTOK    (BATCH * SEQ)          // 4096
#define QK_SCALE2 0.18033688f           // 0.125 * log2(e)

typedef __nv_bfloat16 bf16;

// ---------------------------------------------------------------------------
// Device scratch (no cudaMalloc allowed)
// ---------------------------------------------------------------------------
__device__ __half s_x16[NTOK * HIDDEN];             // X fp16 (qkv GEMM input)
__device__ __half s_w16[3 * HIDDEN * HIDDEN];       // Wq/Wk/Wv^T fp16
__device__ bf16 s_whi[HIDDEN * HIDDEN];             // Wo^T split-bf16
__device__ bf16 s_wlo[HIDDEN * HIDDEN];
__device__ bf16 g_qhi[BATCH * HEADS * SEQ * HDIM];  // [B,H,S,D] (Q pre-scaled)
__device__ bf16 g_qlo[BATCH * HEADS * SEQ * HDIM];
__device__ bf16 g_khi[BATCH * HEADS * SEQ * HDIM];
__device__ bf16 g_klo[BATCH * HEADS * SEQ * HDIM];
__device__ bf16 g_vhi[BATCH * HEADS * SEQ * HDIM];
__device__ bf16 g_vlo[BATCH * HEADS * SEQ * HDIM];
__device__ bf16 g_ohi[NTOK * HIDDEN];               // attention out [B,S,H*D]
__device__ bf16 g_olo[NTOK * HIDDEN];

// ---------------------------------------------------------------------------
// PTX helpers
// ---------------------------------------------------------------------------
__device__ __forceinline__ uint32_t smem_u32(const void* p) {
    uint32_t a;
    asm("{ .reg .u64 t; cvta.to.shared.u64 t, %1; cvt.u32.u64 %0, t; }" : "=r"(a) : "l"(p));
    return a;
}
__device__ __forceinline__ void cp16(uint32_t s, const void* g) {
    asm volatile("cp.async.cg.shared.global [%0], [%1], 16;" :: "r"(s), "l"(g) : "memory");
}
#define CP_COMMIT() asm volatile("cp.async.commit_group;" ::: "memory")
#define CP_WAIT0()  asm volatile("cp.async.wait_group 0;" ::: "memory")
#define CP_WAIT1()  asm volatile("cp.async.wait_group 1;" ::: "memory")

__device__ __forceinline__ void ldsm4(uint32_t& r0, uint32_t& r1, uint32_t& r2, uint32_t& r3, uint32_t a) {
    asm volatile("ldmatrix.sync.aligned.m8n8.x4.shared.b16 {%0,%1,%2,%3}, [%4];"
                 : "=r"(r0), "=r"(r1), "=r"(r2), "=r"(r3) : "r"(a));
}
__device__ __forceinline__ void ldsm4t(uint32_t& r0, uint32_t& r1, uint32_t& r2, uint32_t& r3, uint32_t a) {
    asm volatile("ldmatrix.sync.aligned.m8n8.x4.trans.shared.b16 {%0,%1,%2,%3}, [%4];"
                 : "=r"(r0), "=r"(r1), "=r"(r2), "=r"(r3) : "r"(a));
}
__device__ __forceinline__ void mma_bf16(float d[4], const uint32_t a[4], const uint32_t b[2]) {
    asm volatile(
        "mma.sync.aligned.m16n8k16.row.col.f32.bf16.bf16.f32 "
        "{%0,%1,%2,%3}, {%4,%5,%6,%7}, {%8,%9}, {%0,%1,%2,%3};"
        : "+f"(d[0]), "+f"(d[1]), "+f"(d[2]), "+f"(d[3])
        : "r"(a[0]), "r"(a[1]), "r"(a[2]), "r"(a[3]), "r"(b[0]), "r"(b[1]));
}
__device__ __forceinline__ void mma_f16(float d[4], const uint32_t a[4], const uint32_t b[2]) {
    asm volatile(
        "mma.sync.aligned.m16n8k16.row.col.f32.f16.f16.f32 "
        "{%0,%1,%2,%3}, {%4,%5,%6,%7}, {%8,%9}, {%0,%1,%2,%3};"
        : "+f"(d[0]), "+f"(d[1]), "+f"(d[2]), "+f"(d[3])
        : "r"(a[0]), "r"(a[1]), "r"(a[2]), "r"(a[3]), "r"(b[0]), "r"(b[1]));
}
// split x,y into packed bf16 hi pair + lo pair (packed cvt)
__device__ __forceinline__ void hilo2(float x, float y, uint32_t& hi, uint32_t& lo) {
    __nv_bfloat162 h2 = __floats2bfloat162_rn(x, y);   // x->low, y->high
    float rx = x - __bfloat162float(h2.x);
    float ry = y - __bfloat162float(h2.y);
    __nv_bfloat162 l2 = __floats2bfloat162_rn(rx, ry);
    hi = *reinterpret_cast<uint32_t*>(&h2);
    lo = *reinterpret_cast<uint32_t*>(&l2);
}

// 128B rows, XOR swizzle on the 16B column within the row (all tiles)
__device__ __forceinline__ uint32_t fsw(uint32_t r, uint32_t cb) {
    return r * 128u + ((((cb >> 4) ^ r) & 7u) << 4) + (cb & 15u);
}

// ---------------------------------------------------------------------------
// Pre-convert kernels
// ---------------------------------------------------------------------------
__global__ __launch_bounds__(256) void convert_x(const float* __restrict__ X) {
    size_t i4 = ((size_t)blockIdx.x * 256 + threadIdx.x) * 4;
    float4 v = *(const float4*)&X[i4];
    __half2 a = __floats2half2_rn(v.x, v.y);
    __half2 b = __floats2half2_rn(v.z, v.w);
    *(__half2*)&s_x16[i4]     = a;
    *(__half2*)&s_x16[i4 + 2] = b;
}

// W [k][n] -> Wt [n][k]; z<3 -> fp16 (qkv), z==3 -> split-bf16 (Wo)
__global__ __launch_bounds__(256) void transpose_w(
    const float* __restrict__ w0, const float* __restrict__ w1,
    const float* __restrict__ w2, const float* __restrict__ w3)
{
    __shared__ float t[32][33];
    const int z = blockIdx.z;
    const float* W = (z == 0) ? w0 : (z == 1) ? w1 : (z == 2) ? w2 : w3;
    const int n0 = blockIdx.x * 32, k0 = blockIdx.y * 32;
    const int tx = threadIdx.x, ty = threadIdx.y;   // 32 x 8
#pragma unroll
    for (int i = 0; i < 4; i++)
        t[ty + i * 8][tx] = W[(size_t)(k0 + ty + i * 8) * HIDDEN + n0 + tx];
    __syncthreads();
#pragma unroll
    for (int i = 0; i < 4; i++) {
        int nr = ty + i * 8;
        float v = t[tx][nr];
        if (z < 3) {
            s_w16[(size_t)z * HIDDEN * HIDDEN + (size_t)(n0 + nr) * HIDDEN + k0 + tx] =
                __float2half_rn(v);
        } else {
            bf16 h = __float2bfloat16_rn(v);
            bf16 l = __float2bfloat16_rn(v - __bfloat162float(h));
            s_whi[(size_t)(n0 + nr) * HIDDEN + k0 + tx] = h;
            s_wlo[(size_t)(n0 + nr) * HIDDEN + k0 + tx] = l;
        }
    }
}

// ---------------------------------------------------------------------------
// fp16 single-precision GEMM for QKV: C = X @ Wt^T (per z).
// Block 128x128, BK=64 (128B fp16 rows), 3-stage cp.async,
// 8 warps (warp tile 64x32), 2 CTAs/SM. Epilogue: split-bf16 [B,H,S,D].
// ---------------------------------------------------------------------------
#define QBK     64
#define QKIT    (HIDDEN / QBK)          // 16
#define QT_B    (128 * 128)             // 16384 per tile (128 rows x 128B)
#define QOB     QT_B
#define QSTAGE  (2 * QT_B)              // 32768
#define QNST    3
#define QSMEM   (QNST * QSTAGE)         // 98304 (x2 CTAs = 196K)

__global__ __launch_bounds__(256, 2) void gemm_qkv16()
{
    extern __shared__ __align__(16) char qsm[];
    const uint32_t sb0 = smem_u32(qsm);

    const int tid = threadIdx.x;
    const int lane = tid & 31;
    const int wid = tid >> 5;
    const int g = lane >> 2, tig = lane & 3;
    const int warp_m = wid >> 2;        // 0..1
    const int warp_n = wid & 3;         // 0..3
    const int row0 = blockIdx.y * 128;
    const int col0 = blockIdx.x * 128;
    const int z = blockIdx.z;
    const __half* __restrict__ A = s_x16;
    const __half* __restrict__ B = s_w16 + (size_t)z * HIDDEN * HIDDEN;

    float acc[4][4][4];
#pragma unroll
    for (int mi = 0; mi < 4; mi++)
#pragma unroll
        for (int ni = 0; ni < 4; ni++)
#pragma unroll
            for (int e = 0; e < 4; e++) acc[mi][ni][e] = 0.f;

    auto load_stage = [&](uint32_t sb, int kc) {
        const int k0 = kc * QBK;
#pragma unroll
        for (int i = 0; i < 8; i++) {
            int ci = tid + i * 256;     // 2048 chunks: 1024 A + 1024 B
            int isB = (ci >= 1024);
            int idx = ci & 1023;
            int r = idx >> 3, c = idx & 7;
            uint32_t dst = sb + (isB ? QOB : 0) + fsw((uint32_t)r, (uint32_t)(c * 16));
            const __half* src = (isB ? B + (size_t)(col0 + r) * HIDDEN
                                     : A + (size_t)(row0 + r) * HIDDEN) + k0 + c * 8;
            cp16(dst, src);
        }
    };

    load_stage(sb0,          0);
    CP_COMMIT();
    load_stage(sb0 + QSTAGE, 1);
    CP_COMMIT();

    const uint32_t a_row = (uint32_t)(((lane >> 3) & 1) * 8 + (lane & 7));
    const uint32_t a_cb  = (uint32_t)((lane >> 4) * 16);
    const uint32_t b_row = (uint32_t)((lane >> 4) * 8 + (lane & 7));
    const uint32_t b_cb  = (uint32_t)(((lane >> 3) & 1) * 16);

    int stage = 0;
    for (int kc = 0; kc < QKIT; kc++) {
        CP_WAIT1();
        __syncthreads();
        if (kc + 2 < QKIT)
            load_stage(sb0 + ((stage + 2) % QNST) * QSTAGE, kc + 2);
        CP_COMMIT();

        const uint32_t sb = sb0 + stage * QSTAGE;
#pragma unroll
        for (int ks = 0; ks < 4; ks++) {           // four k16 slices (BK=64)
            const uint32_t cbA = (uint32_t)(ks * 32) + a_cb;
            const uint32_t cbB = (uint32_t)(ks * 32) + b_cb;
            uint32_t ah[4][4];
#pragma unroll
            for (int mi = 0; mi < 4; mi++) {
                uint32_t r = (uint32_t)(warp_m * 64 + mi * 16) + a_row;
                ldsm4(ah[mi][0], ah[mi][1], ah[mi][2], ah[mi][3], sb + fsw(r, cbA));
            }
#pragma unroll
            for (int np = 0; np < 2; np++) {       // n16 pairs (32 cols)
                uint32_t n = (uint32_t)(warp_n * 32 + np * 16) + b_row;
                uint32_t h0, h1, h2, h3;
                ldsm4(h0, h1, h2, h3, sb + QOB + fsw(n, cbB));
                uint32_t b0[2] = {h0, h1}, b1[2] = {h2, h3};
#pragma unroll
                for (int mi = 0; mi < 4; mi++) {
                    mma_f16(acc[mi][np * 2],     ah[mi], b0);
                    mma_f16(acc[mi][np * 2 + 1], ah[mi], b1);
                }
            }
        }
        stage = (stage + 1) % QNST;
    }

    // epilogue: split-bf16 into [B,H,S,D]; Q pre-scaled by QK_SCALE2
    bf16* OutHi = (z == 0) ? g_qhi : (z == 1) ? g_khi : g_vhi;
    bf16* OutLo = (z == 0) ? g_qlo : (z == 1) ? g_klo : g_vlo;
    const float oscale = (z == 0) ? QK_SCALE2 : 1.0f;
#pragma unroll
    for (int mi = 0; mi < 4; mi++) {
        int r = row0 + warp_m * 64 + mi * 16 + g;       // rows r, r+8
#pragma unroll
        for (int ni = 0; ni < 4; ni++) {
            int col = col0 + warp_n * 32 + ni * 8 + tig * 2;
            int h = col >> 6, d = col & 63;
            int b0 = r >> 11, sg0 = r & 2047;
            int b1 = (r + 8) >> 11, sg1 = (r + 8) & 2047;
            size_t i0 = (((size_t)(b0 * HEADS + h)) * SEQ + sg0) * HDIM + d;
            size_t i1 = (((size_t)(b1 * HEADS + h)) * SEQ + sg1) * HDIM + d;
            uint32_t hi, lo;
            hilo2(acc[mi][ni][0] * oscale, acc[mi][ni][1] * oscale, hi, lo);
            *(uint32_t*)&OutHi[i0] = hi;  *(uint32_t*)&OutLo[i0] = lo;
            hilo2(acc[mi][ni][2] * oscale, acc[mi][ni][3] * oscale, hi, lo);
            *(uint32_t*)&OutHi[i1] = hi;  *(uint32_t*)&OutLo[i1] = lo;
        }
    }
}

// ---------------------------------------------------------------------------
// Split-bf16 GEMM (R15-proven) — used for the output projection only.
// Block 256x128xBK32, 8 warps (64x64), 1 CTA/SM, 3-stage dense stages.
// ---------------------------------------------------------------------------
#define GBK     32
#define GKITERS (HIDDEN / GBK)          // 32
#define GA_B    (256 * 128)             // 32768
#define GB_B    (128 * 128)             // 16384
#define OA2     0
#define OB2     GA_B
#define G2STAGE (GA_B + GB_B)           // 49152
#define G2NST   3
#define GSMEM   (G2NST * G2STAGE)       // 147456

__global__ __launch_bounds__(256, 1) void gemm_out(float* __restrict__ OutF)
{
    extern __shared__ __align__(16) char gsm[];
    const uint32_t sb0 = smem_u32(gsm);
    const bf16* __restrict__ Ahi = g_ohi;
    const bf16* __restrict__ Alo = g_olo;
    const bf16* __restrict__ Bhi = s_whi;
    const bf16* __restrict__ Blo = s_wlo;

    const int tid = threadIdx.x;
    const int lane = tid & 31;
    const int wid = tid >> 5;
    const int g = lane >> 2, tig = lane & 3;
    const int warp_m = wid >> 1;        // 0..3
    const int warp_n = wid & 1;         // 0..1
    const int row0 = blockIdx.y * 256;
    const int col0 = blockIdx.x * 128;

    float acc[4][8][4];
#pragma unroll
    for (int mi = 0; mi < 4; mi++)
#pragma unroll
        for (int nj = 0; nj < 8; nj++)
#pragma unroll
            for (int e = 0; e < 4; e++) acc[mi][nj][e] = 0.f;

    auto load_stage = [&](uint32_t sb, int kc) {
        const int k0 = kc * GBK;
#pragma unroll
        for (int i = 0; i < 12; i++) {
            int ci = tid + i * 256;
            int isB = (ci >= 2048);
            int idx = isB ? (ci - 2048) : ci;
            int r = idx >> 3, c = idx & 7;
            uint32_t dst = sb + (isB ? OB2 : OA2) + fsw((uint32_t)r, (uint32_t)(c * 16));
            size_t off = (size_t)((isB ? col0 : row0) + r) * HIDDEN + k0 + (c & 3) * 8;
            const bf16* src;
            if (!isB) src = (c < 4) ? Ahi + off : Alo + off;
            else      src = (c < 4) ? Bhi + off : Blo + off;
            cp16(dst, src);
        }
    };

    load_stage(sb0,           0);
    CP_COMMIT();
    load_stage(sb0 + G2STAGE, 1);
    CP_COMMIT();

    const uint32_t a_row = (uint32_t)(((lane >> 3) & 1) * 8 + (lane & 7));
    const uint32_t a_cb  = (uint32_t)((lane >> 4) * 16);
    const uint32_t b_row = (uint32_t)((lane >> 4) * 8 + (lane & 7));
    const uint32_t b_cb  = (uint32_t)(((lane >> 3) & 1) * 16);

    int stage = 0;
    for (int kc = 0; kc < GKITERS; kc++) {
        CP_WAIT1();
        __syncthreads();
        if (kc + 2 < GKITERS)
            load_stage(sb0 + ((stage + 2) % G2NST) * G2STAGE, kc + 2);
        CP_COMMIT();

        const uint32_t sb = sb0 + stage * G2STAGE;
#pragma unroll
        for (int ks = 0; ks < 2; ks++) {
            const uint32_t cbA = (uint32_t)(ks * 32) + a_cb;
            const uint32_t cbB = (uint32_t)(ks * 32) + b_cb;
            uint32_t bh[8][2], bl[8][2];
#pragma unroll
            for (int ng = 0; ng < 4; ng++) {
                uint32_t n = (uint32_t)(warp_n * 64 + ng * 16) + b_row;
                uint32_t h0, h1, h2, h3, l0, l1, l2, l3;
                ldsm4(h0, h1, h2, h3, sb + OB2 + fsw(n, cbB));
                ldsm4(l0, l1, l2, l3, sb + OB2 + fsw(n, 64u + cbB));
                bh[ng * 2][0] = h0;     bh[ng * 2][1] = h1;
                bh[ng * 2 + 1][0] = h2; bh[ng * 2 + 1][1] = h3;
                bl[ng * 2][0] = l0;     bl[ng * 2][1] = l1;
                bl[ng * 2 + 1][0] = l2; bl[ng * 2 + 1][1] = l3;
            }
#pragma unroll
            for (int mi = 0; mi < 4; mi++) {
                uint32_t r = (uint32_t)(warp_m * 64 + mi * 16) + a_row;
                uint32_t ah[4], al[4];
                ldsm4(ah[0], ah[1], ah[2], ah[3], sb + OA2 + fsw(r, cbA));
                ldsm4(al[0], al[1], al[2], al[3], sb + OA2 + fsw(r, 64u + cbA));
#pragma unroll
                for (int nj = 0; nj < 8; nj++) mma_bf16(acc[mi][nj], ah, bh[nj]);
#pragma unroll
                for (int nj = 0; nj < 8; nj++) mma_bf16(acc[mi][nj], ah, bl[nj]);
#pragma unroll
                for (int nj = 0; nj < 8; nj++) mma_bf16(acc[mi][nj], al, bh[nj]);
            }
        }
        stage = (stage + 1) % G2NST;
    }

#pragma unroll
    for (int mi = 0; mi < 4; mi++) {
        int r = row0 + warp_m * 64 + mi * 16 + g;
#pragma unroll
        for (int nj = 0; nj < 8; nj++) {
            int col = col0 + warp_n * 64 + nj * 8 + tig * 2;
            *(float2*)&OutF[(size_t)r * HIDDEN + col] =
                make_float2(acc[mi][nj][0], acc[mi][nj][1]);
            *(float2*)&OutF[(size_t)(r + 8) * HIDDEN + col] =
                make_float2(acc[mi][nj][2], acc[mi][nj][3]);
        }
    }
}

// ---------------------------------------------------------------------------
// Flash attention, split-bf16, Br=128, Bc=128, 8 warps, 2 KV buffers.
// (unchanged — proven 160 us)
// ---------------------------------------------------------------------------
#define FQ_B   (128 * 128)
#define FKV_B  (128 * 128)
#define OQH    0
#define OQL    FQ_B
#define OKV    (2 * FQ_B)
#define FSTAGE_B (4 * FKV_B)
#define FSMEM  (2 * FQ_B + 2 * FSTAGE_B)   // 163840

__global__ __launch_bounds__(256) void flash_tc()
{
    extern __shared__ __align__(16) char fsm[];
    const uint32_t sb = smem_u32(fsm);

    const int tid = threadIdx.x;
    const int lane = tid & 31;
    const int wid = tid >> 5;
    const int g = lane >> 2, tig = lane & 3;
    const int idx = (int)blockIdx.x;
    const int bh = idx & 31;
    const int bx = (SEQ / 128 - 1) - (idx >> 5);      // 15 .. 0
    const int q0 = bx * 128;
    const size_t bho = (size_t)bh * SEQ * HDIM;
    const int nt = bx + 1;

    {
        const bf16* qsrc[2] = {g_qhi + bho, g_qlo + bho};
#pragma unroll
        for (int m = 0; m < 2; m++)
#pragma unroll
            for (int i = 0; i < 4; i++) {
                int ci = tid + i * 256;
                int r = ci >> 3, c = ci & 7;
                cp16(sb + (m ? OQL : OQH) + fsw(r, c * 16),
                     qsrc[m] + (size_t)(q0 + r) * HDIM + c * 8);
            }
    }
    auto load_kv = [&](int t, int buf) {
        const int j0 = t * 128;
        const bf16* src[4] = {g_khi + bho, g_klo + bho, g_vhi + bho, g_vlo + bho};
        uint32_t base = sb + OKV + buf * FSTAGE_B;
#pragma unroll
        for (int m = 0; m < 4; m++)
#pragma unroll
            for (int i = 0; i < 4; i++) {
                int ci = tid + i * 256;
                int r = ci >> 3, c = ci & 7;
                cp16(base + m * FKV_B + fsw(r, c * 16),
                     src[m] + (size_t)(j0 + r) * HDIM + c * 8);
            }
    };
    load_kv(0, 0);
    CP_COMMIT();
    if (nt > 1) load_kv(1, 1);
    CP_COMMIT();

    const uint32_t a_row = (uint32_t)(((lane >> 3) & 1) * 8 + (lane & 7));
    const uint32_t a_cb  = (uint32_t)((lane >> 4) * 16);
    const uint32_t b_row = (uint32_t)((lane >> 4) * 8 + (lane & 7));
    const uint32_t b_cb  = (uint32_t)(((lane >> 3) & 1) * 16);
    const uint32_t q_row = (uint32_t)(wid * 16) + a_row;

    float m0 = -1e30f, m1 = -1e30f, l0 = 0.f, l1 = 0.f;
    float o[8][4];
#pragma unroll
    for (int dt = 0; dt < 8; dt++)
#pragma unroll
        for (int e = 0; e < 4; e++) o[dt][e] = 0.f;

    for (int t = 0; t < nt; t++) {
        CP_WAIT1();
        __syncthreads();
        const uint32_t kvb = sb + OKV + (t & 1) * FSTAGE_B;

        float s[16][4];
#pragma unroll
        for (int j = 0; j < 16; j++)
#pragma unroll
            for (int e = 0; e < 4; e++) s[j][e] = 0.f;
#pragma unroll
        for (int ks = 0; ks < 4; ks++) {
            const uint32_t cbq = (uint32_t)(ks * 32) + a_cb;
            uint32_t qh[4], ql[4];
            ldsm4(qh[0], qh[1], qh[2], qh[3], sb + OQH + fsw(q_row, cbq));
            ldsm4(ql[0], ql[1], ql[2], ql[3], sb + OQL + fsw(q_row, cbq));
            const uint32_t cb = (uint32_t)(ks * 32) + b_cb;
#pragma unroll
            for (int npp = 0; npp < 4; npp++) {
                uint32_t kh[4][2], kl[4][2];
#pragma unroll
                for (int q = 0; q < 2; q++) {
                    uint32_t n = (uint32_t)((npp * 2 + q) * 16) + b_row;
                    uint32_t h0, h1, h2, h3, l0r, l1r, l2r, l3r;
                    ldsm4(h0, h1, h2, h3, kvb + 0 * FKV_B + fsw(n, cb));
                    ldsm4(l0r, l1r, l2r, l3r, kvb + 1 * FKV_B + fsw(n, cb));
                    kh[q * 2][0] = h0;  kh[q * 2][1] = h1;
                    kh[q * 2 + 1][0] = h2;  kh[q * 2 + 1][1] = h3;
                    kl[q * 2][0] = l0r;  kl[q * 2][1] = l1r;
                    kl[q * 2 + 1][0] = l2r;  kl[q * 2 + 1][1] = l3r;
                }
#pragma unroll
                for (int a = 0; a < 4; a++) mma_bf16(s[npp * 4 + a], qh, kh[a]);
#pragma unroll
                for (int a = 0; a < 4; a++) mma_bf16(s[npp * 4 + a], qh, kl[a]);
#pragma unroll
                for (int a = 0; a < 4; a++) mma_bf16(s[npp * 4 + a], ql, kh[a]);
            }
        }

        if (t == bx) {
            const int j0 = t * 128;
            const int r0 = q0 + wid * 16 + g;
#pragma unroll
            for (int j = 0; j < 16; j++) {
#pragma unroll
                for (int e = 0; e < 4; e++) {
                    int col = j0 + j * 8 + tig * 2 + (e & 1);
                    int row = r0 + ((e >> 1) * 8);
                    if (col > row) s[j][e] = -1e9f;
                }
            }
        }

        float mx0 = -1e30f, mx1 = -1e30f;
#pragma unroll
        for (int j = 0; j < 16; j++) {
            mx0 = fmaxf(mx0, fmaxf(s[j][0], s[j][1]));
            mx1 = fmaxf(mx1, fmaxf(s[j][2], s[j][3]));
        }
        mx0 = fmaxf(mx0, __shfl_xor_sync(0xffffffffu, mx0, 1));
        mx0 = fmaxf(mx0, __shfl_xor_sync(0xffffffffu, mx0, 2));
        mx1 = fmaxf(mx1, __shfl_xor_sync(0xffffffffu, mx1, 1));
        mx1 = fmaxf(mx1, __shfl_xor_sync(0xffffffffu, mx1, 2));
        float mn0 = fmaxf(m0, mx0), mn1 = fmaxf(m1, mx1);
        float al0 = exp2f(m0 - mn0), al1 = exp2f(m1 - mn1);
        m0 = mn0;  m1 = mn1;
#pragma unroll
        for (int dt = 0; dt < 8; dt++) {
            o[dt][0] *= al0; o[dt][1] *= al0;
            o[dt][2] *= al1; o[dt][3] *= al1;
        }
        float sum0 = 0.f, sum1 = 0.f;

#pragma unroll
        for (int kp = 0; kp < 8; kp++) {
            float p00 = exp2f(s[2 * kp][0] - mn0);
            float p01 = exp2f(s[2 * kp][1] - mn0);
            float p02 = exp2f(s[2 * kp][2] - mn1);
            float p03 = exp2f(s[2 * kp][3] - mn1);
            float p10 = exp2f(s[2 * kp + 1][0] - mn0);
            float p11 = exp2f(s[2 * kp + 1][1] - mn0);
            float p12 = exp2f(s[2 * kp + 1][2] - mn1);
            float p13 = exp2f(s[2 * kp + 1][3] - mn1);
            sum0 += p00 + p01 + p10 + p11;
            sum1 += p02 + p03 + p12 + p13;
            uint32_t ph[4], pl[4];
            hilo2(p00, p01, ph[0], pl[0]);
            hilo2(p02, p03, ph[1], pl[1]);
            hilo2(p10, p11, ph[2], pl[2]);
            hilo2(p12, p13, ph[3], pl[3]);
            uint32_t kr = (uint32_t)(kp * 16) + a_row;
#pragma unroll
            for (int npp = 0; npp < 2; npp++) {
                uint32_t vh[4][2], vl[4][2];
#pragma unroll
                for (int q = 0; q < 2; q++) {
                    uint32_t cb = (uint32_t)((npp * 2 + q) * 32) + a_cb;
                    uint32_t v0, v1, v2, v3, w0, w1, w2, w3;
                    ldsm4t(v0, v1, v2, v3, kvb + 2 * FKV_B + fsw(kr, cb));
                    ldsm4t(w0, w1, w2, w3, kvb + 3 * FKV_B + fsw(kr, cb));
                    vh[q * 2][0] = v0;  vh[q * 2][1] = v1;
                    vh[q * 2 + 1][0] = v2;  vh[q * 2 + 1][1] = v3;
                    vl[q * 2][0] = w0;  vl[q * 2][1] = w1;
                    vl[q * 2 + 1][0] = w2;  vl[q * 2 + 1][1] = w3;
                }
#pragma unroll
                for (int a = 0; a < 4; a++) mma_bf16(o[npp * 4 + a], ph, vh[a]);
#pragma unroll
                for (int a = 0; a < 4; a++) mma_bf16(o[npp * 4 + a], ph, vl[a]);
#pragma unroll
                for (int a = 0; a < 4; a++) mma_bf16(o[npp * 4 + a], pl, vh[a]);
            }
        }

        sum0 += __shfl_xor_sync(0xffffffffu, sum0, 1);
        sum0 += __shfl_xor_sync(0xffffffffu, sum0, 2);
        sum1 += __shfl_xor_sync(0xffffffffu, sum1, 1);
        sum1 += __shfl_xor_sync(0xffffffffu, sum1, 2);
        l0 = l0 * al0 + sum0;
        l1 = l1 * al1 + sum1;

        __syncthreads();
        if (t + 2 < nt) load_kv(t + 2, t & 1);
        CP_COMMIT();
    }

    const int b = bh >> 4, h = bh & 15;
    const int s0 = q0 + wid * 16 + g;
    const float i0 = 1.f / l0, i1 = 1.f / l1;
#pragma unroll
    for (int dt = 0; dt < 8; dt++) {
        int d = dt * 8 + tig * 2;
        size_t base0 = ((size_t)(b * SEQ) + s0) * HIDDEN + h * HDIM + d;
        size_t base1 = base0 + (size_t)8 * HIDDEN;
        uint32_t hi, lo;
        hilo2(o[dt][0] * i0, o[dt][1] * i0, hi, lo);
        *(uint32_t*)&g_ohi[base0] = hi;  *(uint32_t*)&g_olo[base0] = lo;
        hilo2(o[dt][2] * i1, o[dt][3] * i1, hi, lo);
        *(uint32_t*)&g_ohi[base1] = hi;  *(uint32_t*)&g_olo[base1] = lo;
    }
}

// ---------------------------------------------------------------------------
// Launch
// ---------------------------------------------------------------------------
extern "C" void kernel_launch(void* const* d_in, const int* in_sizes, int n_in,
                              void* d_out, int out_size)
{
    const float* X  = (const float*)d_in[0];
    // d_in[1] = attention_mask (exact causal; applied analytically)
    const float* Wq = (const float*)d_in[2];
    const float* Wk = (const float*)d_in[3];
    const float* Wv = (const float*)d_in[4];
    const float* Wo = (const float*)d_in[5];
    float* out = (float*)d_out;

    cudaFuncSetAttribute(gemm_qkv16, cudaFuncAttributeMaxDynamicSharedMemorySize, QSMEM);
    cudaFuncSetAttribute(gemm_out,  cudaFuncAttributeMaxDynamicSharedMemorySize, GSMEM);
    cudaFuncSetAttribute(flash_tc,  cudaFuncAttributeMaxDynamicSharedMemorySize, FSMEM);

    convert_x<<<NTOK * HIDDEN / 1024, 256>>>(X);
    transpose_w<<<dim3(32, 32, 4), dim3(32, 8)>>>(Wq, Wk, Wv, Wo);

    gemm_qkv16<<<dim3(HIDDEN / 128, NTOK / 128, 3), 256, QSMEM>>>();

    flash_tc<<<(SEQ / 128) * BATCH * HEADS, 256, FSMEM>>>();

    gemm_out<<<dim3(HIDDEN / 128, NTOK / 256), 256, GSMEM>>>(out);
}

// round 17
// speedup vs baseline: 1.7805x; 1.1570x over previous
#include <cuda_runtime.h>
#include <cuda_bf16.h>
#include <cuda_fp16.h>
#include <cstdint>

#define BATCH   2
#define SEQ     2048
#define HIDDEN  1024
#define HEADS   16
#define HDIM    64
#define NTOK    (BATCH * SEQ)          // 4096
#define QK_SCALE2 0.18033688f           // 0.125 * log2(e)

typedef __nv_bfloat16 bf16;

// ---------------------------------------------------------------------------
// Device scratch (no cudaMalloc allowed)
// ---------------------------------------------------------------------------
__device__ __half s_x16[NTOK * HIDDEN];             // X fp16 (qkv GEMM input)
__device__ __half s_w16[4 * HIDDEN * HIDDEN];       // Wq/Wk/Wv/Wo^T fp16
__device__ bf16 g_qhi[BATCH * HEADS * SEQ * HDIM];  // [B,H,S,D] (Q pre-scaled)
__device__ bf16 g_qlo[BATCH * HEADS * SEQ * HDIM];
__device__ bf16 g_khi[BATCH * HEADS * SEQ * HDIM];
__device__ bf16 g_klo[BATCH * HEADS * SEQ * HDIM];
__device__ bf16 g_vhi[BATCH * HEADS * SEQ * HDIM];
__device__ bf16 g_vlo[BATCH * HEADS * SEQ * HDIM];
__device__ __half g_o16[NTOK * HIDDEN];             // attention out fp16 [B,S,H*D]

// ---------------------------------------------------------------------------
// PTX helpers
// ---------------------------------------------------------------------------
__device__ __forceinline__ uint32_t smem_u32(const void* p) {
    uint32_t a;
    asm("{ .reg .u64 t; cvta.to.shared.u64 t, %1; cvt.u32.u64 %0, t; }" : "=r"(a) : "l"(p));
    return a;
}
__device__ __forceinline__ void cp16(uint32_t s, const void* g) {
    asm volatile("cp.async.cg.shared.global [%0], [%1], 16;" :: "r"(s), "l"(g) : "memory");
}
#define CP_COMMIT() asm volatile("cp.async.commit_group;" ::: "memory")
#define CP_WAIT0()  asm volatile("cp.async.wait_group 0;" ::: "memory")
#define CP_WAIT1()  asm volatile("cp.async.wait_group 1;" ::: "memory")

__device__ __forceinline__ void ldsm4(uint32_t& r0, uint32_t& r1, uint32_t& r2, uint32_t& r3, uint32_t a) {
    asm volatile("ldmatrix.sync.aligned.m8n8.x4.shared.b16 {%0,%1,%2,%3}, [%4];"
                 : "=r"(r0), "=r"(r1), "=r"(r2), "=r"(r3) : "r"(a));
}
__device__ __forceinline__ void ldsm4t(uint32_t& r0, uint32_t& r1, uint32_t& r2, uint32_t& r3, uint32_t a) {
    asm volatile("ldmatrix.sync.aligned.m8n8.x4.trans.shared.b16 {%0,%1,%2,%3}, [%4];"
                 : "=r"(r0), "=r"(r1), "=r"(r2), "=r"(r3) : "r"(a));
}
__device__ __forceinline__ void mma_bf16(float d[4], const uint32_t a[4], const uint32_t b[2]) {
    asm volatile(
        "mma.sync.aligned.m16n8k16.row.col.f32.bf16.bf16.f32 "
        "{%0,%1,%2,%3}, {%4,%5,%6,%7}, {%8,%9}, {%0,%1,%2,%3};"
        : "+f"(d[0]), "+f"(d[1]), "+f"(d[2]), "+f"(d[3])
        : "r"(a[0]), "r"(a[1]), "r"(a[2]), "r"(a[3]), "r"(b[0]), "r"(b[1]));
}
__device__ __forceinline__ void mma_f16(float d[4], const uint32_t a[4], const uint32_t b[2]) {
    asm volatile(
        "mma.sync.aligned.m16n8k16.row.col.f32.f16.f16.f32 "
        "{%0,%1,%2,%3}, {%4,%5,%6,%7}, {%8,%9}, {%0,%1,%2,%3};"
        : "+f"(d[0]), "+f"(d[1]), "+f"(d[2]), "+f"(d[3])
        : "r"(a[0]), "r"(a[1]), "r"(a[2]), "r"(a[3]), "r"(b[0]), "r"(b[1]));
}
// split x,y into packed bf16 hi pair + lo pair (packed cvt)
__device__ __forceinline__ void hilo2(float x, float y, uint32_t& hi, uint32_t& lo) {
    __nv_bfloat162 h2 = __floats2bfloat162_rn(x, y);   // x->low, y->high
    float rx = x - __bfloat162float(h2.x);
    float ry = y - __bfloat162float(h2.y);
    __nv_bfloat162 l2 = __floats2bfloat162_rn(rx, ry);
    hi = *reinterpret_cast<uint32_t*>(&h2);
    lo = *reinterpret_cast<uint32_t*>(&l2);
}

// 128B rows, XOR swizzle on the 16B column within the row (all tiles)
__device__ __forceinline__ uint32_t fsw(uint32_t r, uint32_t cb) {
    return r * 128u + ((((cb >> 4) ^ r) & 7u) << 4) + (cb & 15u);
}

// ---------------------------------------------------------------------------
// Pre-convert kernels
// ---------------------------------------------------------------------------
__global__ __launch_bounds__(256) void convert_x(const float* __restrict__ X) {
    size_t i4 = ((size_t)blockIdx.x * 256 + threadIdx.x) * 4;
    float4 v = *(const float4*)&X[i4];
    __half2 a = __floats2half2_rn(v.x, v.y);
    __half2 b = __floats2half2_rn(v.z, v.w);
    *(__half2*)&s_x16[i4]     = a;
    *(__half2*)&s_x16[i4 + 2] = b;
}

// W [k][n] -> Wt [n][k] fp16, 32x32 tiles (all four weights)
__global__ __launch_bounds__(256) void transpose_w(
    const float* __restrict__ w0, const float* __restrict__ w1,
    const float* __restrict__ w2, const float* __restrict__ w3)
{
    __shared__ float t[32][33];
    const int z = blockIdx.z;
    const float* W = (z == 0) ? w0 : (z == 1) ? w1 : (z == 2) ? w2 : w3;
    const int n0 = blockIdx.x * 32, k0 = blockIdx.y * 32;
    const int tx = threadIdx.x, ty = threadIdx.y;   // 32 x 8
#pragma unroll
    for (int i = 0; i < 4; i++)
        t[ty + i * 8][tx] = W[(size_t)(k0 + ty + i * 8) * HIDDEN + n0 + tx];
    __syncthreads();
#pragma unroll
    for (int i = 0; i < 4; i++) {
        int nr = ty + i * 8;
        s_w16[(size_t)z * HIDDEN * HIDDEN + (size_t)(n0 + nr) * HIDDEN + k0 + tx] =
            __float2half_rn(t[tx][nr]);
    }
}

// ---------------------------------------------------------------------------
// fp16 single-precision GEMM core: 128x128, BK=64, 3-stage, 8 warps, 2 CTAs/SM.
// ---------------------------------------------------------------------------
#define QBK     64
#define QKIT    (HIDDEN / QBK)          // 16
#define QT_B    (128 * 128)             // 16384 per tile (128 rows x 128B)
#define QOB     QT_B
#define QSTAGE  (2 * QT_B)              // 32768
#define QNST    3
#define QSMEM   (QNST * QSTAGE)         // 98304 (x2 CTAs = 196K)

// computes acc for this thread's fragment; A,B fp16 row-major [.][HIDDEN]
__device__ __forceinline__ void gemm16_mainloop(
    const __half* __restrict__ A, const __half* __restrict__ B,
    int row0, int col0, float acc[4][4][4])
{
    extern __shared__ __align__(16) char qsm[];
    const uint32_t sb0 = smem_u32(qsm);
    const int tid = threadIdx.x;
    const int lane = tid & 31;
    const int wid = tid >> 5;
    const int warp_m = wid >> 2;        // 0..1
    const int warp_n = wid & 3;         // 0..3

    auto load_stage = [&](uint32_t sb, int kc) {
        const int k0 = kc * QBK;
#pragma unroll
        for (int i = 0; i < 8; i++) {
            int ci = tid + i * 256;     // 2048 chunks: 1024 A + 1024 B
            int isB = (ci >= 1024);
            int idx = ci & 1023;
            int r = idx >> 3, c = idx & 7;
            uint32_t dst = sb + (isB ? QOB : 0) + fsw((uint32_t)r, (uint32_t)(c * 16));
            const __half* src = (isB ? B + (size_t)(col0 + r) * HIDDEN
                                     : A + (size_t)(row0 + r) * HIDDEN) + k0 + c * 8;
            cp16(dst, src);
        }
    };

    load_stage(sb0,          0);
    CP_COMMIT();
    load_stage(sb0 + QSTAGE, 1);
    CP_COMMIT();

    const uint32_t a_row = (uint32_t)(((lane >> 3) & 1) * 8 + (lane & 7));
    const uint32_t a_cb  = (uint32_t)((lane >> 4) * 16);
    const uint32_t b_row = (uint32_t)((lane >> 4) * 8 + (lane & 7));
    const uint32_t b_cb  = (uint32_t)(((lane >> 3) & 1) * 16);

    int stage = 0;
    for (int kc = 0; kc < QKIT; kc++) {
        CP_WAIT1();
        __syncthreads();
        if (kc + 2 < QKIT)
            load_stage(sb0 + ((stage + 2) % QNST) * QSTAGE, kc + 2);
        CP_COMMIT();

        const uint32_t sb = sb0 + stage * QSTAGE;
#pragma unroll
        for (int ks = 0; ks < 4; ks++) {           // four k16 slices (BK=64)
            const uint32_t cbA = (uint32_t)(ks * 32) + a_cb;
            const uint32_t cbB = (uint32_t)(ks * 32) + b_cb;
            uint32_t ah[4][4];
#pragma unroll
            for (int mi = 0; mi < 4; mi++) {
                uint32_t r = (uint32_t)(warp_m * 64 + mi * 16) + a_row;
                ldsm4(ah[mi][0], ah[mi][1], ah[mi][2], ah[mi][3], sb + fsw(r, cbA));
            }
#pragma unroll
            for (int np = 0; np < 2; np++) {       // n16 pairs (32 cols)
                uint32_t n = (uint32_t)(warp_n * 32 + np * 16) + b_row;
                uint32_t h0, h1, h2, h3;
                ldsm4(h0, h1, h2, h3, sb + QOB + fsw(n, cbB));
                uint32_t b0[2] = {h0, h1}, b1[2] = {h2, h3};
#pragma unroll
                for (int mi = 0; mi < 4; mi++) {
                    mma_f16(acc[mi][np * 2],     ah[mi], b0);
                    mma_f16(acc[mi][np * 2 + 1], ah[mi], b1);
                }
            }
        }
        stage = (stage + 1) % QNST;
    }
}

__global__ __launch_bounds__(256, 2) void gemm_qkv16()
{
    const int tid = threadIdx.x;
    const int lane = tid & 31;
    const int wid = tid >> 5;
    const int g = lane >> 2, tig = lane & 3;
    const int warp_m = wid >> 2, warp_n = wid & 3;
    const int row0 = blockIdx.y * 128;
    const int col0 = blockIdx.x * 128;
    const int z = blockIdx.z;

    float acc[4][4][4];
#pragma unroll
    for (int mi = 0; mi < 4; mi++)
#pragma unroll
        for (int ni = 0; ni < 4; ni++)
#pragma unroll
            for (int e = 0; e < 4; e++) acc[mi][ni][e] = 0.f;

    gemm16_mainloop(s_x16, s_w16 + (size_t)z * HIDDEN * HIDDEN, row0, col0, acc);

    // epilogue: split-bf16 into [B,H,S,D]; Q pre-scaled by QK_SCALE2
    bf16* OutHi = (z == 0) ? g_qhi : (z == 1) ? g_khi : g_vhi;
    bf16* OutLo = (z == 0) ? g_qlo : (z == 1) ? g_klo : g_vlo;
    const float oscale = (z == 0) ? QK_SCALE2 : 1.0f;
#pragma unroll
    for (int mi = 0; mi < 4; mi++) {
        int r = row0 + warp_m * 64 + mi * 16 + g;       // rows r, r+8
#pragma unroll
        for (int ni = 0; ni < 4; ni++) {
            int col = col0 + warp_n * 32 + ni * 8 + tig * 2;
            int h = col >> 6, d = col & 63;
            int b0 = r >> 11, sg0 = r & 2047;
            int b1 = (r + 8) >> 11, sg1 = (r + 8) & 2047;
            size_t i0 = (((size_t)(b0 * HEADS + h)) * SEQ + sg0) * HDIM + d;
            size_t i1 = (((size_t)(b1 * HEADS + h)) * SEQ + sg1) * HDIM + d;
            uint32_t hi, lo;
            hilo2(acc[mi][ni][0] * oscale, acc[mi][ni][1] * oscale, hi, lo);
            *(uint32_t*)&OutHi[i0] = hi;  *(uint32_t*)&OutLo[i0] = lo;
            hilo2(acc[mi][ni][2] * oscale, acc[mi][ni][3] * oscale, hi, lo);
            *(uint32_t*)&OutHi[i1] = hi;  *(uint32_t*)&OutLo[i1] = lo;
        }
    }
}

__global__ __launch_bounds__(256, 2) void gemm_out16(float* __restrict__ OutF)
{
    const int tid = threadIdx.x;
    const int lane = tid & 31;
    const int wid = tid >> 5;
    const int g = lane >> 2, tig = lane & 3;
    const int warp_m = wid >> 2, warp_n = wid & 3;
    const int row0 = blockIdx.y * 128;
    const int col0 = blockIdx.x * 128;

    float acc[4][4][4];
#pragma unroll
    for (int mi = 0; mi < 4; mi++)
#pragma unroll
        for (int ni = 0; ni < 4; ni++)
#pragma unroll
            for (int e = 0; e < 4; e++) acc[mi][ni][e] = 0.f;

    gemm16_mainloop(g_o16, s_w16 + (size_t)3 * HIDDEN * HIDDEN, row0, col0, acc);

#pragma unroll
    for (int mi = 0; mi < 4; mi++) {
        int r = row0 + warp_m * 64 + mi * 16 + g;
#pragma unroll
        for (int ni = 0; ni < 4; ni++) {
            int col = col0 + warp_n * 32 + ni * 8 + tig * 2;
            *(float2*)&OutF[(size_t)r * HIDDEN + col] =
                make_float2(acc[mi][ni][0], acc[mi][ni][1]);
            *(float2*)&OutF[(size_t)(r + 8) * HIDDEN + col] =
                make_float2(acc[mi][ni][2], acc[mi][ni][3]);
        }
    }
}

// ---------------------------------------------------------------------------
// Flash attention, split-bf16, Br=128, Bc=128, 8 warps, 2 KV buffers.
// Epilogue writes fp16 (feeds gemm_out16). Otherwise proven 160 us design.
// ---------------------------------------------------------------------------
#define FQ_B   (128 * 128)
#define FKV_B  (128 * 128)
#define OQH    0
#define OQL    FQ_B
#define OKV    (2 * FQ_B)
#define FSTAGE_B (4 * FKV_B)
#define FSMEM  (2 * FQ_B + 2 * FSTAGE_B)   // 163840

__global__ __launch_bounds__(256) void flash_tc()
{
    extern __shared__ __align__(16) char fsm[];
    const uint32_t sb = smem_u32(fsm);

    const int tid = threadIdx.x;
    const int lane = tid & 31;
    const int wid = tid >> 5;
    const int g = lane >> 2, tig = lane & 3;
    const int idx = (int)blockIdx.x;
    const int bh = idx & 31;
    const int bx = (SEQ / 128 - 1) - (idx >> 5);      // 15 .. 0
    const int q0 = bx * 128;
    const size_t bho = (size_t)bh * SEQ * HDIM;
    const int nt = bx + 1;

    {
        const bf16* qsrc[2] = {g_qhi + bho, g_qlo + bho};
#pragma unroll
        for (int m = 0; m < 2; m++)
#pragma unroll
            for (int i = 0; i < 4; i++) {
                int ci = tid + i * 256;
                int r = ci >> 3, c = ci & 7;
                cp16(sb + (m ? OQL : OQH) + fsw(r, c * 16),
                     qsrc[m] + (size_t)(q0 + r) * HDIM + c * 8);
            }
    }
    auto load_kv = [&](int t, int buf) {
        const int j0 = t * 128;
        const bf16* src[4] = {g_khi + bho, g_klo + bho, g_vhi + bho, g_vlo + bho};
        uint32_t base = sb + OKV + buf * FSTAGE_B;
#pragma unroll
        for (int m = 0; m < 4; m++)
#pragma unroll
            for (int i = 0; i < 4; i++) {
                int ci = tid + i * 256;
                int r = ci >> 3, c = ci & 7;
                cp16(base + m * FKV_B + fsw(r, c * 16),
                     src[m] + (size_t)(j0 + r) * HDIM + c * 8);
            }
    };
    load_kv(0, 0);
    CP_COMMIT();
    if (nt > 1) load_kv(1, 1);
    CP_COMMIT();

    const uint32_t a_row = (uint32_t)(((lane >> 3) & 1) * 8 + (lane & 7));
    const uint32_t a_cb  = (uint32_t)((lane >> 4) * 16);
    const uint32_t b_row = (uint32_t)((lane >> 4) * 8 + (lane & 7));
    const uint32_t b_cb  = (uint32_t)(((lane >> 3) & 1) * 16);
    const uint32_t q_row = (uint32_t)(wid * 16) + a_row;

    float m0 = -1e30f, m1 = -1e30f, l0 = 0.f, l1 = 0.f;
    float o[8][4];
#pragma unroll
    for (int dt = 0; dt < 8; dt++)
#pragma unroll
        for (int e = 0; e < 4; e++) o[dt][e] = 0.f;

    for (int t = 0; t < nt; t++) {
        CP_WAIT1();
        __syncthreads();
        const uint32_t kvb = sb + OKV + (t & 1) * FSTAGE_B;

        float s[16][4];
#pragma unroll
        for (int j = 0; j < 16; j++)
#pragma unroll
            for (int e = 0; e < 4; e++) s[j][e] = 0.f;
#pragma unroll
        for (int ks = 0; ks < 4; ks++) {
            const uint32_t cbq = (uint32_t)(ks * 32) + a_cb;
            uint32_t qh[4], ql[4];
            ldsm4(qh[0], qh[1], qh[2], qh[3], sb + OQH + fsw(q_row, cbq));
            ldsm4(ql[0], ql[1], ql[2], ql[3], sb + OQL + fsw(q_row, cbq));
            const uint32_t cb = (uint32_t)(ks * 32) + b_cb;
#pragma unroll
            for (int npp = 0; npp < 4; npp++) {
                uint32_t kh[4][2], kl[4][2];
#pragma unroll
                for (int q = 0; q < 2; q++) {
                    uint32_t n = (uint32_t)((npp * 2 + q) * 16) + b_row;
                    uint32_t h0, h1, h2, h3, l0r, l1r, l2r, l3r;
                    ldsm4(h0, h1, h2, h3, kvb + 0 * FKV_B + fsw(n, cb));
                    ldsm4(l0r, l1r, l2r, l3r, kvb + 1 * FKV_B + fsw(n, cb));
                    kh[q * 2][0] = h0;  kh[q * 2][1] = h1;
                    kh[q * 2 + 1][0] = h2;  kh[q * 2 + 1][1] = h3;
                    kl[q * 2][0] = l0r;  kl[q * 2][1] = l1r;
                    kl[q * 2 + 1][0] = l2r;  kl[q * 2 + 1][1] = l3r;
                }
#pragma unroll
                for (int a = 0; a < 4; a++) mma_bf16(s[npp * 4 + a], qh, kh[a]);
#pragma unroll
                for (int a = 0; a < 4; a++) mma_bf16(s[npp * 4 + a], qh, kl[a]);
#pragma unroll
                for (int a = 0; a < 4; a++) mma_bf16(s[npp * 4 + a], ql, kh[a]);
            }
        }

        if (t == bx) {
            const int j0 = t * 128;
            const int r0 = q0 + wid * 16 + g;
#pragma unroll
            for (int j = 0; j < 16; j++) {
#pragma unroll
                for (int e = 0; e < 4; e++) {
                    int col = j0 + j * 8 + tig * 2 + (e & 1);
                    int row = r0 + ((e >> 1) * 8);
                    if (col > row) s[j][e] = -1e9f;
                }
            }
        }

        float mx0 = -1e30f, mx1 = -1e30f;
#pragma unroll
        for (int j = 0; j < 16; j++) {
            mx0 = fmaxf(mx0, fmaxf(s[j][0], s[j][1]));
            mx1 = fmaxf(mx1, fmaxf(s[j][2], s[j][3]));
        }
        mx0 = fmaxf(mx0, __shfl_xor_sync(0xffffffffu, mx0, 1));
        mx0 = fmaxf(mx0, __shfl_xor_sync(0xffffffffu, mx0, 2));
        mx1 = fmaxf(mx1, __shfl_xor_sync(0xffffffffu, mx1, 1));
        mx1 = fmaxf(mx1, __shfl_xor_sync(0xffffffffu, mx1, 2));
        float mn0 = fmaxf(m0, mx0), mn1 = fmaxf(m1, mx1);
        float al0 = exp2f(m0 - mn0), al1 = exp2f(m1 - mn1);
        m0 = mn0;  m1 = mn1;
#pragma unroll
        for (int dt = 0; dt < 8; dt++) {
            o[dt][0] *= al0; o[dt][1] *= al0;
            o[dt][2] *= al1; o[dt][3] *= al1;
        }
        float sum0 = 0.f, sum1 = 0.f;

#pragma unroll
        for (int kp = 0; kp < 8; kp++) {
            float p00 = exp2f(s[2 * kp][0] - mn0);
            float p01 = exp2f(s[2 * kp][1] - mn0);
            float p02 = exp2f(s[2 * kp][2] - mn1);
            float p03 = exp2f(s[2 * kp][3] - mn1);
            float p10 = exp2f(s[2 * kp + 1][0] - mn0);
            float p11 = exp2f(s[2 * kp + 1][1] - mn0);
            float p12 = exp2f(s[2 * kp + 1][2] - mn1);
            float p13 = exp2f(s[2 * kp + 1][3] - mn1);
            sum0 += p00 + p01 + p10 + p11;
            sum1 += p02 + p03 + p12 + p13;
            uint32_t ph[4], pl[4];
            hilo2(p00, p01, ph[0], pl[0]);
            hilo2(p02, p03, ph[1], pl[1]);
            hilo2(p10, p11, ph[2], pl[2]);
            hilo2(p12, p13, ph[3], pl[3]);
            uint32_t kr = (uint32_t)(kp * 16) + a_row;
#pragma unroll
            for (int npp = 0; npp < 2; npp++) {
                uint32_t vh[4][2], vl[4][2];
#pragma unroll
                for (int q = 0; q < 2; q++) {
                    uint32_t cb = (uint32_t)((npp * 2 + q) * 32) + a_cb;
                    uint32_t v0, v1, v2, v3, w0, w1, w2, w3;
                    ldsm4t(v0, v1, v2, v3, kvb + 2 * FKV_B + fsw(kr, cb));
                    ldsm4t(w0, w1, w2, w3, kvb + 3 * FKV_B + fsw(kr, cb));
                    vh[q * 2][0] = v0;  vh[q * 2][1] = v1;
                    vh[q * 2 + 1][0] = v2;  vh[q * 2 + 1][1] = v3;
                    vl[q * 2][0] = w0;  vl[q * 2][1] = w1;
                    vl[q * 2 + 1][0] = w2;  vl[q * 2 + 1][1] = w3;
                }
#pragma unroll
                for (int a = 0; a < 4; a++) mma_bf16(o[npp * 4 + a], ph, vh[a]);
#pragma unroll
                for (int a = 0; a < 4; a++) mma_bf16(o[npp * 4 + a], ph, vl[a]);
#pragma unroll
                for (int a = 0; a < 4; a++) mma_bf16(o[npp * 4 + a], pl, vh[a]);
            }
        }

        sum0 += __shfl_xor_sync(0xffffffffu, sum0, 1);
        sum0 += __shfl_xor_sync(0xffffffffu, sum0, 2);
        sum1 += __shfl_xor_sync(0xffffffffu, sum1, 1);
        sum1 += __shfl_xor_sync(0xffffffffu, sum1, 2);
        l0 = l0 * al0 + sum0;
        l1 = l1 * al1 + sum1;

        __syncthreads();
        if (t + 2 < nt) load_kv(t + 2, t & 1);
        CP_COMMIT();
    }

    // ---- epilogue: O/l -> fp16 at [b][s][h*64+d] ----
    const int b = bh >> 4, h = bh & 15;
    const int s0 = q0 + wid * 16 + g;
    const float i0 = 1.f / l0, i1 = 1.f / l1;
#pragma unroll
    for (int dt = 0; dt < 8; dt++) {
        int d = dt * 8 + tig * 2;
        size_t base0 = ((size_t)(b * SEQ) + s0) * HIDDEN + h * HDIM + d;
        size_t base1 = base0 + (size_t)8 * HIDDEN;
        *(__half2*)&g_o16[base0] = __floats2half2_rn(o[dt][0] * i0, o[dt][1] * i0);
        *(__half2*)&g_o16[base1] = __floats2half2_rn(o[dt][2] * i1, o[dt][3] * i1);
    }
}

// ---------------------------------------------------------------------------
// Launch
// ---------------------------------------------------------------------------
extern "C" void kernel_launch(void* const* d_in, const int* in_sizes, int n_in,
                              void* d_out, int out_size)
{
    const float* X  = (const float*)d_in[0];
    // d_in[1] = attention_mask (exact causal; applied analytically)
    const float* Wq = (const float*)d_in[2];
    const float* Wk = (const float*)d_in[3];
    const float* Wv = (const float*)d_in[4];
    const float* Wo = (const float*)d_in[5];
    float* out = (float*)d_out;

    cudaFuncSetAttribute(gemm_qkv16, cudaFuncAttributeMaxDynamicSharedMemorySize, QSMEM);
    cudaFuncSetAttribute(gemm_out16, cudaFuncAttributeMaxDynamicSharedMemorySize, QSMEM);
    cudaFuncSetAttribute(flash_tc,   cudaFuncAttributeMaxDynamicSharedMemorySize, FSMEM);

    convert_x<<<NTOK * HIDDEN / 1024, 256>>>(X);
    transpose_w<<<dim3(32, 32, 4), dim3(32, 8)>>>(Wq, Wk, Wv, Wo);

    gemm_qkv16<<<dim3(HIDDEN / 128, NTOK / 128, 3), 256, QSMEM>>>();

    flash_tc<<<(SEQ / 128) * BATCH * HEADS, 256, FSMEM>>>();

    gemm_out16<<<dim3(HIDDEN / 128, NTOK / 128), 256, QSMEM>>>(out);
}